// round 15
// baseline (speedup 1.0000x reference)
#include <cuda_runtime.h>
#include <cuda_bf16.h>

#define H 128
#define F 166
#define NMAX 100000
#define EMAX 600000

typedef unsigned int u32;
typedef unsigned long long u64;

// ---------------- scratch (static device memory; no allocs) ----------------
__device__ float g_h[(size_t)NMAX * H];
__device__ float g_r[(size_t)NMAX * H];
__device__ float g_z[(size_t)NMAX * H];
__device__ float g_hc[(size_t)NMAX * H];
__device__ float g_hlrec[(size_t)NMAX * H];
__device__ float g_hlhis[(size_t)NMAX * H];
__device__ float g_h2[(size_t)NMAX * H];
__device__ float g_h3[(size_t)NMAX * H];
__device__ float g_nt[NMAX];
__device__ u32 g_degrec[NMAX], g_deghis[NMAX];
__device__ float g_disrec[NMAX], g_dishis[NMAX];
__device__ unsigned char g_upd[NMAX];
// small histograms: L1 = tb>>20 (4096), L2 = (tb>>8)&0xFFF (4096), L3 = tb&0xFF (256)
__device__ u32 g_hist1[4096], g_hist2a[4096], g_hist2b[4096], g_hist3a[256], g_hist3b[256];
__device__ u32 g_offs[NMAX], g_cursor[NMAX], g_bsum[512];
__device__ u32 g_esrc[EMAX];
__device__ float g_ecoef[EMAX];
// composed attention weight Wc = Wo @ Wv and bias bc = Wo @ bv + bo
__device__ float g_wc[H * H];
__device__ float g_bc[H];

// pre-converted weights: packed bf16 pairs, hi and lo parts
#define WOFF_IN  0
#define WOFF_IHR 12288
#define WOFF_IHZ (WOFF_IHR + 8192)
#define WOFF_IHC (WOFF_IHZ + 8192)
#define WOFF_HHR (WOFF_IHC + 8192)
#define WOFF_HHZ (WOFF_HHR + 8192)
#define WOFF_HHC (WOFF_HHZ + 8192)
#define WOFF_GR  (WOFF_HHC + 8192)
#define WOFF_GH  (WOFF_GR + 8192)
#define WOFF_VO  (WOFF_GH + 8192)
#define WOFF_W1  (WOFF_VO + 8192)
#define WTOT     (WOFF_W1 + 4096)
__device__ u32 g_whi[WTOT], g_wlo[WTOT];

// scalars: 0 ntmin 1 ntmax
// 2 bin1A 3 rankA  4 bin1B 5 rankB
// 6 bin2A 7 rankA2 8 bin2B 9 rankB2
// 10 med_bits
// 12 bin3A 13 -    14 bin3B 15 -
__device__ u32 g_scal[16];

// ---------------- generic helpers ----------------
__device__ __forceinline__ float wsum(float v) {
    #pragma unroll
    for (int o = 16; o; o >>= 1) v += __shfl_xor_sync(0xffffffffu, v, o);
    return v;
}
__device__ __forceinline__ float qsum(float v) {   // sum over 4-lane group
    v += __shfl_xor_sync(0xffffffffu, v, 1);
    v += __shfl_xor_sync(0xffffffffu, v, 2);
    return v;
}
__device__ __forceinline__ float sigmoidf_(float x) { return 1.0f / (1.0f + expf(-x)); }
__device__ __forceinline__ u32 smem_u32(const void* p) {
    u32 a;
    asm("{ .reg .u64 t; cvta.to.shared.u64 t, %1; cvt.u32.u64 %0, t; }" : "=r"(a) : "l"(p));
    return a;
}
// round-to-nearest split (used for weights, done once)
__device__ __forceinline__ void split2(float v0, float v1, u32& hip, u32& lop) {
    __nv_bfloat16 h0 = __float2bfloat16(v0);
    __nv_bfloat16 h1 = __float2bfloat16(v1);
    __nv_bfloat16 g0 = __float2bfloat16(v0 - __bfloat162float(h0));
    __nv_bfloat16 g1 = __float2bfloat16(v1 - __bfloat162float(h1));
    hip = ((u32)__bfloat16_as_ushort(h1) << 16) | (u32)__bfloat16_as_ushort(h0);
    lop = ((u32)__bfloat16_as_ushort(g1) << 16) | (u32)__bfloat16_as_ushort(g0);
}
// truncating split (cheap; lo capture is exact, dropped term ~2^-17)
__device__ __forceinline__ void split2t(float2 v, u32& hip, u32& lop) {
    u32 bx = __float_as_uint(v.x), by = __float_as_uint(v.y);
    hip = __byte_perm(bx, by, 0x7632);
    float l0 = v.x - __uint_as_float(bx & 0xFFFF0000u);
    float l1 = v.y - __uint_as_float(by & 0xFFFF0000u);
    lop = __byte_perm(__float_as_uint(l0), __float_as_uint(l1), 0x7632);
}

// mma.sync m16n8k16 row.col f32 <- bf16 x bf16 + f32   (baseline sm_80+ PTX)
__device__ __forceinline__ void mma16816(float* d, const u32* a, const u32* b) {
    asm volatile(
        "mma.sync.aligned.m16n8k16.row.col.f32.bf16.bf16.f32 "
        "{%0,%1,%2,%3}, {%4,%5,%6,%7}, {%8,%9}, {%0,%1,%2,%3};"
        : "+f"(d[0]), "+f"(d[1]), "+f"(d[2]), "+f"(d[3])
        : "r"(a[0]), "r"(a[1]), "r"(a[2]), "r"(a[3]), "r"(b[0]), "r"(b[1]));
}
__device__ __forceinline__ void ldsm4(u32* r, u32 addr) {
    asm volatile("ldmatrix.sync.aligned.m8n8.x4.shared.b16 {%0,%1,%2,%3}, [%4];"
                 : "=r"(r[0]), "=r"(r[1]), "=r"(r[2]), "=r"(r[3]) : "r"(addr));
}

// ---------------- attention weight composition: Wc = Wo @ Wv ----------------
__global__ void k_compose(const float* __restrict__ Wv, const float* __restrict__ Wo,
                          const float* __restrict__ bv, const float* __restrict__ bo,
                          float* __restrict__ Wc, float* __restrict__ bc) {
    __shared__ float srow[H];
    int j = blockIdx.x, t = threadIdx.x;
    srow[t] = Wo[j * H + t];
    __syncthreads();
    float s = 0.0f;
    #pragma unroll 8
    for (int q = 0; q < H; q++) s = fmaf(srow[q], Wv[q * H + t], s);
    Wc[j * H + t] = s;
    if (t == 0) {
        float b = bo[j];
        for (int q = 0; q < H; q++) b = fmaf(srow[q], bv[q], b);
        bc[j] = b;
    }
}

// ---------------- weight pre-conversion ----------------
struct WC {
    const float* src[12];
    int K[12], stride[12], end[12];
    int total;
};

__global__ void k_wconv(WC wc, u32* __restrict__ whi, u32* __restrict__ wlo) {
    int gi = blockIdx.x * blockDim.x + threadIdx.x;
    int gs = gridDim.x * blockDim.x;
    for (; gi < wc.total; gi += gs) {
        int m = 0;
        #pragma unroll
        for (int q = 0; q < 11; q++) if (gi >= wc.end[m]) m++;
        int base = m ? wc.end[m - 1] : 0;
        int local = gi - base;
        int st = wc.stride[m];
        int row = local / st, cp = local - row * st;
        int k = cp * 2, K = wc.K[m];
        const float* s = wc.src[m] + (size_t)row * K;
        float v0 = (k < K) ? s[k] : 0.0f;
        float v1 = (k + 1 < K) ? s[k + 1] : 0.0f;
        u32 hip, lop;
        split2(v0, v1, hip, lop);
        whi[gi] = hip; wlo[gi] = lop;
    }
}

// ---------------- init ----------------
__global__ void k_init(int N) {
    int tid = blockIdx.x * blockDim.x + threadIdx.x;
    int stride = gridDim.x * blockDim.x;
    for (int i = tid; i < N; i += stride) {
        g_nt[i] = 0.0f; g_upd[i] = 0; g_degrec[i] = 0; g_deghis[i] = 0;
    }
    for (int i = tid; i < 4096; i += stride) {
        g_hist1[i] = 0; g_hist2a[i] = 0; g_hist2b[i] = 0;
        if (i < 256) { g_hist3a[i] = 0; g_hist3b[i] = 0; }
    }
    if (tid == 0) { g_scal[0] = 0x7F800000u; g_scal[1] = 0u; }
}

// ---------------- edge pass 1: nt max, upd flags, L1 hist ----------------
__global__ void k_edge1(const int* __restrict__ ei, const float* __restrict__ ts, int E) {
    __shared__ u32 sh[4096];
    int tid = threadIdx.x;
    for (int i = tid; i < 4096; i += 256) sh[i] = 0;
    __syncthreads();
    int T = gridDim.x * blockDim.x;
    int g0 = blockIdx.x * blockDim.x + tid;
    int nfull = E / T;
    for (int it = 0; it < nfull; it++) {
        int e = g0 + it * T;
        int r = ei[e], c = ei[E + e];
        u32 tb = __float_as_uint(ts[e]);
        atomicMax((u32*)&g_nt[c], tb);   // ts >= 0 so bit order == float order
        g_upd[r] = 1; g_upd[c] = 1;
        u32 bin = tb >> 20;
        u32 mask = __match_any_sync(0xffffffffu, bin);
        if ((u32)(tid & 31) == (u32)(__ffs(mask) - 1))
            atomicAdd(&sh[bin], (u32)__popc(mask));
    }
    int e = g0 + nfull * T;
    bool valid = e < E;
    u32 am = __ballot_sync(0xffffffffu, valid);
    if (valid) {
        int r = ei[e], c = ei[E + e];
        u32 tb = __float_as_uint(ts[e]);
        atomicMax((u32*)&g_nt[c], tb);
        g_upd[r] = 1; g_upd[c] = 1;
        u32 bin = tb >> 20;
        u32 mask = __match_any_sync(am, bin);
        if ((u32)(tid & 31) == (u32)(__ffs(mask) - 1))
            atomicAdd(&sh[bin], (u32)__popc(mask));
    }
    __syncthreads();
    for (int i = tid; i < 4096; i += 256) {
        u32 v = sh[i];
        if (v) atomicAdd(&g_hist1[i], v);
    }
}

// ---------------- L2 hist pass (conditional on L1 bins) ----------------
__global__ void k_hl2(const float* __restrict__ ts, int E) {
    __shared__ u32 sa[4096], sb[4096];
    int tid = threadIdx.x;
    for (int i = tid; i < 4096; i += 256) { sa[i] = 0; sb[i] = 0; }
    __syncthreads();
    u32 binA = g_scal[2], binB = g_scal[4];
    int gs = gridDim.x * blockDim.x;
    for (int e = blockIdx.x * blockDim.x + tid; e < E; e += gs) {
        u32 tb = __float_as_uint(ts[e]);
        u32 b1 = tb >> 20, b2 = (tb >> 8) & 0xFFFu;
        if (b1 == binA) atomicAdd(&sa[b2], 1u);
        if (b1 == binB) atomicAdd(&sb[b2], 1u);
    }
    __syncthreads();
    for (int i = tid; i < 4096; i += 256) {
        u32 va = sa[i]; if (va) atomicAdd(&g_hist2a[i], va);
        u32 vb = sb[i]; if (vb) atomicAdd(&g_hist2b[i], vb);
    }
}

// ---------------- L3 hist pass ----------------
__global__ void k_hl3(const float* __restrict__ ts, int E) {
    __shared__ u32 sa[256], sb[256];
    int tid = threadIdx.x;
    if (tid < 256) { sa[tid] = 0; sb[tid] = 0; }
    __syncthreads();
    u32 pA = (g_scal[2] << 12) | g_scal[6];
    u32 pB = (g_scal[4] << 12) | g_scal[8];
    int gs = gridDim.x * blockDim.x;
    for (int e = blockIdx.x * blockDim.x + tid; e < E; e += gs) {
        u32 tb = __float_as_uint(ts[e]);
        u32 hi = tb >> 8, b3 = tb & 0xFFu;
        if (hi == pA) atomicAdd(&sa[b3], 1u);
        if (hi == pB) atomicAdd(&sb[b3], 1u);
    }
    __syncthreads();
    if (tid < 256) {
        u32 va = sa[tid]; if (va) atomicAdd(&g_hist3a[tid], va);
        u32 vb = sb[tid]; if (vb) atomicAdd(&g_hist3b[tid], vb);
    }
}

// ---------------- dual k-th select (block 0 -> A, block 1 -> B) -----------
__global__ void k_sel2(const u32* __restrict__ histA, const u32* __restrict__ histB,
                       int per,
                       u32 kA_imm, int kA_idx, int oA,
                       u32 kB_imm, int kB_idx, int oB) {
    __shared__ u32 sh[256];
    __shared__ u32 s_t;
    const u32* hist = blockIdx.x ? histB : histA;
    u32 k_imm = blockIdx.x ? kB_imm : kA_imm;
    int kidx = blockIdx.x ? kB_idx : kA_idx;
    int oidx = blockIdx.x ? oB : oA;
    int t = threadIdx.x;
    u32 k = (kidx >= 0) ? g_scal[kidx] : k_imm;
    u32 s = 0;
    for (int j = 0; j < per; j++) s += hist[t * per + j];
    u32 x = s;
    sh[t] = x; __syncthreads();
    for (int off = 1; off < 256; off <<= 1) {
        u32 a = (t >= off) ? sh[t - off] : 0u;
        __syncthreads();
        x += a; sh[t] = x;
        __syncthreads();
    }
    if (k < x && k >= x - s) s_t = (u32)t;
    __syncthreads();
    if ((u32)t == s_t) {
        u32 run = x - s;
        for (int j = 0; j < per; j++) {
            u32 hv = hist[t * per + j];
            if (k < run + hv) { g_scal[oidx] = (u32)(t * per + j); g_scal[oidx + 1] = k - run; break; }
            run += hv;
        }
    }
}

// ---------------- reconstruct median from 3-level bins ----------------
__global__ void k_med3() {
    u32 v0 = (g_scal[2] << 20) | (g_scal[6] << 8) | g_scal[12];
    u32 v1 = (g_scal[4] << 20) | (g_scal[8] << 8) | g_scal[14];
    g_scal[10] = __float_as_uint(0.5f * (__uint_as_float(v0) + __uint_as_float(v1)));
}

// ---------------- min/max over nt ----------------
__global__ void k_minmax(int N) {
    int tid = blockIdx.x * blockDim.x + threadIdx.x;
    int stride = gridDim.x * blockDim.x;
    u32 mn = 0x7F800000u, mx = 0u;
    for (int i = tid; i < N; i += stride) {
        u32 b = __float_as_uint(g_nt[i]);
        mn = min(mn, b); mx = max(mx, b);
    }
    #pragma unroll
    for (int o = 16; o; o >>= 1) {
        mn = min(mn, __shfl_xor_sync(0xffffffffu, mn, o));
        mx = max(mx, __shfl_xor_sync(0xffffffffu, mx, o));
    }
    if ((threadIdx.x & 31) == 0) {
        atomicMin(&g_scal[0], mn);
        atomicMax(&g_scal[1], mx);
    }
}

// ---------------- per-path in-degree ----------------
__global__ void k_deg(const int* __restrict__ ei, const float* __restrict__ ts, int E) {
    int e = blockIdx.x * blockDim.x + threadIdx.x;
    if (e >= E) return;
    float med = __uint_as_float(g_scal[10]);
    int c = ei[E + e];
    if (ts[e] >= med) atomicAdd(&g_degrec[c], 1u);
    else atomicAdd(&g_deghis[c], 1u);
}

// ---------------- CSR build ----------------
__global__ void k_scan1(int N) {
    __shared__ u32 sh[1024];
    int t = threadIdx.x;
    int i = blockIdx.x * 1024 + t;
    u32 v = (i < N) ? (g_degrec[i] + g_deghis[i]) : 0u;
    sh[t] = v;
    __syncthreads();
    for (int off = 1; off < 1024; off <<= 1) {
        u32 a = (t >= off) ? sh[t - off] : 0u;
        __syncthreads();
        sh[t] += a;
        __syncthreads();
    }
    if (i < N) g_offs[i] = sh[t];
    if (t == 1023) g_bsum[blockIdx.x] = sh[1023];
}

__global__ void k_scan2(int NB) {
    if (threadIdx.x == 0) {
        u32 run = 0;
        for (int b = 0; b < NB; b++) { u32 t2 = g_bsum[b]; g_bsum[b] = run; run += t2; }
    }
}

__global__ void k_scan3(int N) {
    int i = blockIdx.x * blockDim.x + threadIdx.x;
    if (i >= N) return;
    u32 cr = g_degrec[i], ch = g_deghis[i];
    u32 excl = g_offs[i] - (cr + ch) + g_bsum[i >> 10];
    g_offs[i] = excl;
    g_cursor[i] = excl;
    g_disrec[i] = rsqrtf((float)cr + 1.0f);
    g_dishis[i] = rsqrtf((float)ch + 1.0f);
}

__global__ void k_fill(const int* __restrict__ ei, const float* __restrict__ ts, int E) {
    int e = blockIdx.x * blockDim.x + threadIdx.x;
    if (e >= E) return;
    float med = __uint_as_float(g_scal[10]);
    int r = ei[e], c = ei[E + e];
    bool rec = ts[e] >= med;
    float coef = rec ? (g_disrec[r] * g_disrec[c]) : (g_dishis[r] * g_dishis[c]);
    u32 p = atomicAdd(&g_cursor[c], 1u);
    g_esrc[p] = ((u32)r << 1) | (rec ? 1u : 0u);
    g_ecoef[p] = coef;
}

// ================= HMMA split-bf16 GEMM ====================================
// C[i,j] = epi( sum_k A[i,k]*W[j,k] (+ A2[i,k]*W2[j,k]) )
struct Epi {
    const float* bias;
    const float* bias2;
    const float* wtime;
    const float* ex1;
    const float* ex2;
    const float* ex3;
    const float* mem;
    const unsigned char* upd;
    const float* nt;
};

// smem: 4 tiles [128 rows][72 bf16] (stride 144 B; conflict-free ldmatrix rows)
#define TSTR 144
#define AHI_OFF 0
#define ALO_OFF 18432
#define WHI_OFF 36864
#define WLO_OFF 55296
#define SMEMSZ  73728

// stage one [128 rows][64] f32 A-chunk into hi/lo bf16 tiles (truncating split)
__device__ __forceinline__ void stageA(const float* __restrict__ src, int nrows_valid,
                                       int row0, int Ksrc, int kbase,
                                       char* smem, int tid) {
    for (int idx = tid; idx < 128 * 32; idx += 256) {
        int r = idx >> 5, cp = idx & 31;
        int k = kbase + cp * 2;
        float2 v = make_float2(0.0f, 0.0f);
        int gr = row0 + r;
        if (gr < nrows_valid) {
            if (k + 1 < Ksrc) v = *(const float2*)(src + (size_t)gr * Ksrc + k);
            else if (k < Ksrc) v.x = src[(size_t)gr * Ksrc + k];
        }
        u32 hip, lop;
        split2t(v, hip, lop);
        int off = r * TSTR + cp * 4;
        *(u32*)(smem + AHI_OFF + off) = hip;
        *(u32*)(smem + ALO_OFF + off) = lop;
    }
}

template <int NOUT, int MODE>
__device__ __forceinline__ void epi2(int i, int c, float v0, float v1,
                                     const Epi& ep, float ntn, float* __restrict__ C) {
    if (MODE == 1) {
        v0 += ep.bias[c]; v1 += ep.bias[c + 1];
    } else if (MODE == 3) {
        v0 = sigmoidf_(v0 + ep.bias[c] + ep.bias2[c]);
        v1 = sigmoidf_(v1 + ep.bias[c + 1] + ep.bias2[c + 1]);
    } else if (MODE == 4) {
        float2 m2 = *(const float2*)&ep.mem[(size_t)i * NOUT + c];
        v0 = fmaxf(v0 + ep.bias[c] + ntn * ep.wtime[c] + ep.bias2[c], 0.0f) + m2.x;
        v1 = fmaxf(v1 + ep.bias[c + 1] + ntn * ep.wtime[c + 1] + ep.bias2[c + 1], 0.0f) + m2.y;
    } else if (MODE == 5) {
        float2 hc2 = *(const float2*)&ep.ex1[(size_t)i * NOUT + c];
        float2 r2  = *(const float2*)&ep.ex2[(size_t)i * NOUT + c];
        float2 z2  = *(const float2*)&ep.ex3[(size_t)i * NOUT + c];
        float2 m2  = *(const float2*)&ep.mem[(size_t)i * NOUT + c];
        bool u = ep.upd[i] != 0;
        float cc0 = tanhf(v0 + ep.bias[c] + r2.x * hc2.x);
        float cc1 = tanhf(v1 + ep.bias[c + 1] + r2.y * hc2.y);
        v0 = u ? (1.0f - z2.x) * cc0 + z2.x * m2.x : m2.x;
        v1 = u ? (1.0f - z2.y) * cc1 + z2.y * m2.y : m2.y;
    }
    *(float2*)&C[(size_t)i * NOUT + c] = make_float2(v0, v1);
}

template <int KSRC, int NOUT, int MODE, bool DUAL>
__global__ void __launch_bounds__(256, 3)
k_tgemm(const float* __restrict__ A, u32 woff,
        const float* __restrict__ A2, u32 woff2,
        const u32* __restrict__ whi, const u32* __restrict__ wlo,
        int N, Epi ep, float* __restrict__ C) {
    extern __shared__ char smem[];
    const u32 sbase = smem_u32(smem);
    const int tid = threadIdx.x;
    const int wid = tid >> 5, lane = tid & 31;
    const int row0 = blockIdx.x * 128;
    constexpr int NCH = (KSRC + 63) / 64;
    constexpr int STRU = NCH * 32;
    constexpr int NT = NOUT / 8;
    const int laneg = lane >> 2, kq = (lane & 3) * 2;

    float acc[NT][4];
    #pragma unroll
    for (int n = 0; n < NT; n++)
        #pragma unroll
        for (int q = 0; q < 4; q++) acc[n][q] = 0.0f;

    // ldmatrix row-address offsets for this lane
    const u32 aoff = (u32)((wid * 16 + (lane & 15)) * TSTR + ((lane >> 4) << 4));
    const u32 boff0 = (u32)(((((lane >> 4) & 1) * 8) + (lane & 7)) * TSTR + (((lane >> 3) & 1) << 4));

    #pragma unroll
    for (int pass = 0; pass < (DUAL ? 2 : 1); pass++) {
        const float* Ap = pass ? A2 : A;
        const u32 wo = pass ? woff2 : woff;
        for (int ch = 0; ch < NCH; ch++) {
            if (pass || ch) __syncthreads();
            stageA(Ap, N, row0, KSRC, ch * 64, smem, tid);
            for (int idx = tid; idx < NOUT * 8; idx += 256) {
                int r2 = idx >> 3, q = idx & 7;
                size_t gs = (size_t)wo + (size_t)r2 * STRU + ch * 32 + q * 4;
                uint4 hv = *(const uint4*)(whi + gs);
                uint4 lv = *(const uint4*)(wlo + gs);
                *(uint4*)(smem + WHI_OFF + r2 * TSTR + q * 16) = hv;
                *(uint4*)(smem + WLO_OFF + r2 * TSTR + q * 16) = lv;
            }
            __syncthreads();
            #pragma unroll
            for (int kt = 0; kt < 4; kt++) {
                u32 ko = (u32)(kt * 32);
                u32 ah[4], al[4];
                ldsm4(ah, sbase + AHI_OFF + aoff + ko);
                ldsm4(al, sbase + ALO_OFF + aoff + ko);
                #pragma unroll
                for (int j = 0; j < NT / 2; j++) {
                    u32 bh[4], bl4[4];
                    u32 bo = boff0 + (u32)(j * 16 * TSTR) + ko;
                    ldsm4(bh, sbase + WHI_OFF + bo);
                    ldsm4(bl4, sbase + WLO_OFF + bo);
                    mma16816(acc[2 * j], ah, bh);
                    mma16816(acc[2 * j], ah, bl4);
                    mma16816(acc[2 * j], al, bh);
                    mma16816(acc[2 * j + 1], ah, bh + 2);
                    mma16816(acc[2 * j + 1], ah, bl4 + 2);
                    mma16816(acc[2 * j + 1], al, bh + 2);
                }
            }
        }
    }

    // ---- epilogue ----
    int i0 = row0 + wid * 16 + laneg;
    int i1 = i0 + 8;

    if (MODE == 7) {
        // classifier: relu(acc + b1) then dot with W2 (ex1), bias2 = b2 -> C = logits[N][2]
        float d00 = 0, d10 = 0, d01 = 0, d11 = 0;
        #pragma unroll
        for (int nt = 0; nt < NT; nt++) {
            int c = nt * 8 + kq;
            float w20 = ep.ex1[c], w21 = ep.ex1[c + 1];
            float w30 = ep.ex1[64 + c], w31 = ep.ex1[64 + c + 1];
            float b0 = ep.bias[c], b1v = ep.bias[c + 1];
            float v0 = fmaxf(acc[nt][0] + b0, 0.0f);
            float v1 = fmaxf(acc[nt][1] + b1v, 0.0f);
            d00 += v0 * w20 + v1 * w21;
            d10 += v0 * w30 + v1 * w31;
            v0 = fmaxf(acc[nt][2] + b0, 0.0f);
            v1 = fmaxf(acc[nt][3] + b1v, 0.0f);
            d01 += v0 * w20 + v1 * w21;
            d11 += v0 * w30 + v1 * w31;
        }
        d00 = qsum(d00); d10 = qsum(d10); d01 = qsum(d01); d11 = qsum(d11);
        if ((lane & 3) == 0) {
            float b20 = ep.bias2[0], b21 = ep.bias2[1];
            if (i0 < N) { C[(size_t)i0 * 2] = d00 + b20; C[(size_t)i0 * 2 + 1] = d10 + b21; }
            if (i1 < N) { C[(size_t)i1 * 2] = d01 + b20; C[(size_t)i1 * 2 + 1] = d11 + b21; }
        }
    } else if (MODE == 8) {
        // v = acc + bc + h2 residual; LayerNorm over row; C = h3
        float s0 = 0.0f, s1 = 0.0f;
        #pragma unroll
        for (int nt = 0; nt < NT; nt++) {
            int c = nt * 8 + kq;
            float b0 = ep.bias[c], b1v = ep.bias[c + 1];
            float2 e0 = (i0 < N) ? *(const float2*)&ep.ex1[(size_t)i0 * NOUT + c] : make_float2(0, 0);
            float2 e1 = (i1 < N) ? *(const float2*)&ep.ex1[(size_t)i1 * NOUT + c] : make_float2(0, 0);
            acc[nt][0] += b0 + e0.x;  acc[nt][1] += b1v + e0.y;
            acc[nt][2] += b0 + e1.x;  acc[nt][3] += b1v + e1.y;
            s0 += acc[nt][0] + acc[nt][1];
            s1 += acc[nt][2] + acc[nt][3];
        }
        float mean0 = qsum(s0) * (1.0f / H);
        float mean1 = qsum(s1) * (1.0f / H);
        float vs0 = 0.0f, vs1 = 0.0f;
        #pragma unroll
        for (int nt = 0; nt < NT; nt++) {
            float d;
            d = acc[nt][0] - mean0; vs0 += d * d;
            d = acc[nt][1] - mean0; vs0 += d * d;
            d = acc[nt][2] - mean1; vs1 += d * d;
            d = acc[nt][3] - mean1; vs1 += d * d;
        }
        float inv0 = rsqrtf(qsum(vs0) * (1.0f / H) + 1e-5f);
        float inv1 = rsqrtf(qsum(vs1) * (1.0f / H) + 1e-5f);
        #pragma unroll
        for (int nt = 0; nt < NT; nt++) {
            int c = nt * 8 + kq;
            float gv0 = ep.ex2[c], gv1 = ep.ex2[c + 1];
            float bv0 = ep.ex3[c], bv1 = ep.ex3[c + 1];
            if (i0 < N) {
                float o0 = (acc[nt][0] - mean0) * inv0 * gv0 + bv0;
                float o1 = (acc[nt][1] - mean0) * inv0 * gv1 + bv1;
                *(float2*)&C[(size_t)i0 * NOUT + c] = make_float2(o0, o1);
            }
            if (i1 < N) {
                float o0 = (acc[nt][2] - mean1) * inv1 * gv0 + bv0;
                float o1 = (acc[nt][3] - mean1) * inv1 * gv1 + bv1;
                *(float2*)&C[(size_t)i1 * NOUT + c] = make_float2(o0, o1);
            }
        }
    } else {
        float ntn0 = 0.0f, ntn1 = 0.0f;
        if (MODE == 4) {
            float tmin = __uint_as_float(g_scal[0]);
            float tmax = __uint_as_float(g_scal[1]);
            float inv = 1.0f / (tmax - tmin + 1e-8f);
            bool norm = tmax > tmin;
            if (i0 < N) { float t = ep.nt[i0]; ntn0 = norm ? (t - tmin) * inv : t; }
            if (i1 < N) { float t = ep.nt[i1]; ntn1 = norm ? (t - tmin) * inv : t; }
        }
        #pragma unroll
        for (int nt = 0; nt < NT; nt++) {
            int c = nt * 8 + kq;
            if (i0 < N) epi2<NOUT, MODE>(i0, c, acc[nt][0], acc[nt][1], ep, ntn0, C);
            if (i1 < N) epi2<NOUT, MODE>(i1, c, acc[nt][2], acc[nt][3], ep, ntn1, C);
        }
    }
}

// ---------------- fused GCN gather + path softmax mix + LayerNorm ---------
__global__ void k_gatherp(int N, const float* __restrict__ b_gr, const float* __restrict__ b_gh,
                          const float* __restrict__ lng, const float* __restrict__ lnb) {
    int gw = (blockIdx.x * blockDim.x + threadIdx.x) >> 5;
    int lane = threadIdx.x & 31;
    if (gw >= N) return;
    int i = gw;
    u32 start = g_offs[i];
    u32 cnt = g_degrec[i] + g_deghis[i];
    float4 ar = make_float4(0, 0, 0, 0), ah = make_float4(0, 0, 0, 0);
    for (u32 k = start; k < start + cnt; k++) {
        u32 pk = g_esrc[k];
        float cf = g_ecoef[k];
        int s = (int)(pk >> 1);
        if (pk & 1u) {
            float4 v = *(const float4*)&g_hlrec[(size_t)s * H + lane * 4];
            ar.x += v.x * cf; ar.y += v.y * cf; ar.z += v.z * cf; ar.w += v.w * cf;
        } else {
            float4 v = *(const float4*)&g_hlhis[(size_t)s * H + lane * 4];
            ah.x += v.x * cf; ah.y += v.y * cf; ah.z += v.z * cf; ah.w += v.w * cf;
        }
    }
    float fr = g_disrec[i] * g_disrec[i];
    float fh = g_dishis[i] * g_dishis[i];
    float4 sr = *(const float4*)&g_hlrec[(size_t)i * H + lane * 4];
    float4 sh = *(const float4*)&g_hlhis[(size_t)i * H + lane * 4];
    float4 br = *(const float4*)&b_gr[lane * 4];
    float4 bh = *(const float4*)&b_gh[lane * 4];
    float4 hr, hh;
    hr.x = ar.x + sr.x * fr + br.x; hr.y = ar.y + sr.y * fr + br.y;
    hr.z = ar.z + sr.z * fr + br.z; hr.w = ar.w + sr.w * fr + br.w;
    hh.x = ah.x + sh.x * fh + bh.x; hh.y = ah.y + sh.y * fh + bh.y;
    hh.z = ah.z + sh.z * fh + bh.z; hh.w = ah.w + sh.w * fh + bh.w;
    // path softmax mix + LN (fused)
    float s0 = wsum(hr.x + hr.y + hr.z + hr.w) * (1.0f / H);
    float s1 = wsum(hh.x + hh.y + hh.z + hh.w) * (1.0f / H);
    float m = fmaxf(s0, s1);
    float e0 = expf(s0 - m), e1 = expf(s1 - m);
    float w0 = e0 / (e0 + e1), w1 = e1 / (e0 + e1);
    float4 t;
    t.x = hr.x * w0 + hh.x * w1; t.y = hr.y * w0 + hh.y * w1;
    t.z = hr.z * w0 + hh.z * w1; t.w = hr.w * w0 + hh.w * w1;
    float mean = wsum(t.x + t.y + t.z + t.w) * (1.0f / H);
    float4 d;
    d.x = t.x - mean; d.y = t.y - mean; d.z = t.z - mean; d.w = t.w - mean;
    float var = wsum(d.x * d.x + d.y * d.y + d.z * d.z + d.w * d.w) * (1.0f / H);
    float inv = rsqrtf(var + 1e-5f);
    float4 gv = *(const float4*)&lng[lane * 4];
    float4 bv = *(const float4*)&lnb[lane * 4];
    float4 o;
    o.x = d.x * inv * gv.x + bv.x; o.y = d.y * inv * gv.y + bv.y;
    o.z = d.z * inv * gv.z + bv.z; o.w = d.w * inv * gv.w + bv.w;
    *(float4*)&g_h2[(size_t)i * H + lane * 4] = o;
}

// ---------------- host launcher ----------------
template <int KSRC, int NOUT, int MODE, bool DUAL>
static void tg(const float* A, u32 woff, const float* A2, u32 woff2,
               const u32* whi, const u32* wlo, int N, const Epi& ep, float* C) {
    cudaFuncSetAttribute(k_tgemm<KSRC, NOUT, MODE, DUAL>,
                         cudaFuncAttributeMaxDynamicSharedMemorySize, SMEMSZ);
    k_tgemm<KSRC, NOUT, MODE, DUAL><<<(N + 127) / 128, 256, SMEMSZ>>>(
        A, woff, A2, woff2, whi, wlo, N, ep, C);
}

extern "C" void kernel_launch(void* const* d_in, const int* in_sizes, int n_in,
                              void* d_out, int out_size) {
    const float* x       = (const float*)d_in[0];
    const int*   ei      = (const int*)d_in[1];
    const float* ts      = (const float*)d_in[2];
    const float* mem     = (const float*)d_in[3];
    const float* W_in    = (const float*)d_in[4];
    const float* b_in    = (const float*)d_in[5];
    const float* W_time  = (const float*)d_in[6];
    const float* b_time  = (const float*)d_in[7];
    const float* W_ih    = (const float*)d_in[8];
    const float* W_hh    = (const float*)d_in[9];
    const float* b_ih    = (const float*)d_in[10];
    const float* b_hh    = (const float*)d_in[11];
    const float* W_gr    = (const float*)d_in[12];
    const float* b_gr    = (const float*)d_in[13];
    const float* W_gh    = (const float*)d_in[14];
    const float* b_gh    = (const float*)d_in[15];
    const float* ln_pa_g = (const float*)d_in[16];
    const float* ln_pa_b = (const float*)d_in[17];
    const float* Wv      = (const float*)d_in[18];
    const float* bv      = (const float*)d_in[19];
    const float* Wo      = (const float*)d_in[20];
    const float* bo      = (const float*)d_in[21];
    const float* ln_at_g = (const float*)d_in[22];
    const float* ln_at_b = (const float*)d_in[23];
    const float* W1      = (const float*)d_in[24];
    const float* b1      = (const float*)d_in[25];
    const float* W2p     = (const float*)d_in[26];
    const float* b2      = (const float*)d_in[27];

    const int E = in_sizes[2];
    const int N = in_sizes[0] / F;
    float* out_logits = (float*)d_out;
    float* out_mem = (float*)d_out + (size_t)2 * N;

    float *p_h, *p_r, *p_z, *p_hc, *p_hlrec, *p_hlhis, *p_h2, *p_h3, *p_nt;
    float *p_wc, *p_bc;
    unsigned char* p_upd;
    u32 *p_h1, *p_h2a, *p_h2b, *p_h3a, *p_h3b, *p_whi, *p_wlo;
    cudaGetSymbolAddress((void**)&p_h, g_h);
    cudaGetSymbolAddress((void**)&p_r, g_r);
    cudaGetSymbolAddress((void**)&p_z, g_z);
    cudaGetSymbolAddress((void**)&p_hc, g_hc);
    cudaGetSymbolAddress((void**)&p_hlrec, g_hlrec);
    cudaGetSymbolAddress((void**)&p_hlhis, g_hlhis);
    cudaGetSymbolAddress((void**)&p_h2, g_h2);
    cudaGetSymbolAddress((void**)&p_h3, g_h3);
    cudaGetSymbolAddress((void**)&p_nt, g_nt);
    cudaGetSymbolAddress((void**)&p_upd, g_upd);
    cudaGetSymbolAddress((void**)&p_h1, g_hist1);
    cudaGetSymbolAddress((void**)&p_h2a, g_hist2a);
    cudaGetSymbolAddress((void**)&p_h2b, g_hist2b);
    cudaGetSymbolAddress((void**)&p_h3a, g_hist3a);
    cudaGetSymbolAddress((void**)&p_h3b, g_hist3b);
    cudaGetSymbolAddress((void**)&p_whi, g_whi);
    cudaGetSymbolAddress((void**)&p_wlo, g_wlo);
    cudaGetSymbolAddress((void**)&p_wc, g_wc);
    cudaGetSymbolAddress((void**)&p_bc, g_bc);

    const u32 k0 = (u32)((E - 1) / 2);
    const u32 k1 = (u32)(E / 2);
    const int EB = (E + 255) / 256;
    const int NB1024 = (N + 1023) / 1024;
    const int NWB = (N * 32 + 255) / 256;

    // weight conversion descriptor: 11 real entries (VO uses composed g_wc)
    WC wc;
    const float* wsrcs[11] = {W_in, W_ih, W_ih + H * H, W_ih + 2 * H * H,
                              W_hh, W_hh + H * H, W_hh + 2 * H * H,
                              W_gr, W_gh, p_wc, W1};
    int wK[11]    = {F, H, H, H, H, H, H, H, H, H, H};
    int wrows[11] = {H, H, H, H, H, H, H, H, H, H, 64};
    int run = 0;
    for (int m = 0; m < 11; m++) {
        wc.src[m] = wsrcs[m];
        wc.K[m] = wK[m];
        wc.stride[m] = ((wK[m] + 63) / 64) * 32;
        run += wrows[m] * wc.stride[m];
        wc.end[m] = run;
    }
    wc.src[11] = W1; wc.K[11] = H; wc.stride[11] = 64; wc.end[11] = run;
    wc.total = run;

    // ---- preprocessing ----
    k_init<<<256, 256>>>(N);                                       // 1
    k_compose<<<H, H>>>(Wv, Wo, bv, bo, p_wc, p_bc);               // 2
    k_wconv<<<128, 256>>>(wc, p_whi, p_wlo);                       // 3
    k_edge1<<<1184, 256>>>(ei, ts, E);                             // 4
    k_minmax<<<592, 256>>>(N);                                     // 5
    {
        Epi ep{}; ep.bias = b_hh + 2 * H;                          // 6
        tg<H, H, 1, false>(mem, WOFF_HHC, nullptr, 0, p_whi, p_wlo, N, ep, p_hc);
    }
    k_sel2<<<2, 256>>>(p_h1, p_h1, 16, k0, -1, 2, k1, -1, 4);
    k_hl2<<<888, 256>>>(ts, E);
    k_sel2<<<2, 256>>>(p_h2a, p_h2b, 16, 0, 3, 6, 0, 5, 8);
    k_hl3<<<888, 256>>>(ts, E);
    k_sel2<<<2, 256>>>(p_h3a, p_h3b, 1, 0, 7, 12, 0, 9, 14);
    k_med3<<<1, 1>>>();
    k_deg<<<EB, 256>>>(ei, ts, E);
    k_scan1<<<NB1024, 1024>>>(N);
    k_scan2<<<1, 1>>>(NB1024);
    k_scan3<<<(N + 255) / 256, 256>>>(N);
    k_fill<<<EB, 256>>>(ei, ts, E);

    // ---- h = relu(x@W_in^T + b_in + nt*W_time + b_time) + memory ----
    {
        Epi ep{}; ep.bias = b_in; ep.bias2 = b_time; ep.wtime = W_time; ep.mem = mem; ep.nt = p_nt;
        tg<F, H, 4, false>(x, WOFF_IN, nullptr, 0, p_whi, p_wlo, N, ep, p_h);
    }
    // ---- GRU gates ----
    {
        Epi ep{}; ep.bias = b_ih; ep.bias2 = b_hh;
        tg<H, H, 3, true>(p_h, WOFF_IHR, mem, WOFF_HHR, p_whi, p_wlo, N, ep, p_r);
    }
    {
        Epi ep{}; ep.bias = b_ih + H; ep.bias2 = b_hh + H;
        tg<H, H, 3, true>(p_h, WOFF_IHZ, mem, WOFF_HHZ, p_whi, p_wlo, N, ep, p_z);
    }
    {
        Epi ep{}; ep.bias = b_ih + 2 * H; ep.ex1 = p_hc; ep.ex2 = p_r; ep.ex3 = p_z;
        ep.mem = mem; ep.upd = p_upd;
        tg<H, H, 5, false>(p_h, WOFF_IHC, nullptr, 0, p_whi, p_wlo, N, ep, out_mem);
    }
    // ---- GCN linears + fused gather/pathagg ----
    {
        Epi ep{};
        tg<H, H, 0, false>(p_h, WOFF_GR, nullptr, 0, p_whi, p_wlo, N, ep, p_hlrec);
        tg<H, H, 0, false>(p_h, WOFF_GH, nullptr, 0, p_whi, p_wlo, N, ep, p_hlhis);
    }
    k_gatherp<<<NWB, 256>>>(N, b_gr, b_gh, ln_pa_g, ln_pa_b);
    // ---- attention composed GEMM + residual + LN fused -> h3 ----
    {
        Epi ep{}; ep.bias = p_bc; ep.ex1 = p_h2; ep.ex2 = ln_at_g; ep.ex3 = ln_at_b;
        tg<H, H, 8, false>(p_h2, WOFF_VO, nullptr, 0, p_whi, p_wlo, N, ep, p_h3);
    }
    // ---- classifier + logits fused ----
    {
        Epi ep{}; ep.bias = b1; ep.ex1 = W2p; ep.bias2 = b2;
        tg<H, 64, 7, false>(p_h3, WOFF_W1, nullptr, 0, p_whi, p_wlo, N, ep, out_logits);
    }
}

// round 16
// speedup vs baseline: 1.1253x; 1.1253x over previous
#include <cuda_runtime.h>
#include <cuda_bf16.h>

#define H 128
#define F 166
#define NMAX 100000
#define EMAX 600000

typedef unsigned int u32;
typedef unsigned long long u64;

// ---------------- scratch (static device memory; no allocs) ----------------
__device__ float g_h[(size_t)NMAX * H];
__device__ float g_r[(size_t)NMAX * H];
__device__ float g_z[(size_t)NMAX * H];
__device__ float g_hc[(size_t)NMAX * H];
__device__ float g_hlrec[(size_t)NMAX * H];
__device__ float g_hlhis[(size_t)NMAX * H];
__device__ float g_h2[(size_t)NMAX * H];
__device__ float g_h3[(size_t)NMAX * H];
__device__ float g_nt[NMAX];
__device__ u32 g_degrec[NMAX], g_deghis[NMAX];
__device__ float g_disrec[NMAX], g_dishis[NMAX];
__device__ unsigned char g_upd[NMAX];
// small histograms: L1 = tb>>20 (4096), L2 = (tb>>8)&0xFFF (4096), L3 = tb&0xFF (256)
__device__ u32 g_hist1[4096], g_hist2a[4096], g_hist2b[4096], g_hist3a[256], g_hist3b[256];
__device__ u32 g_offs[NMAX], g_cursor[NMAX], g_bsum[512];
__device__ u32 g_esrc[EMAX];
__device__ float g_ecoef[EMAX];
// composed attention weight Wc = Wo @ Wv and bias bc = Wo @ bv + bo
__device__ float g_wc[H * H];
__device__ float g_bc[H];

// pre-converted weights: packed bf16 pairs, hi and lo parts
#define WOFF_IN  0
#define WOFF_IHR 12288
#define WOFF_IHZ (WOFF_IHR + 8192)
#define WOFF_IHC (WOFF_IHZ + 8192)
#define WOFF_HHR (WOFF_IHC + 8192)
#define WOFF_HHZ (WOFF_HHR + 8192)
#define WOFF_HHC (WOFF_HHZ + 8192)
#define WOFF_GR  (WOFF_HHC + 8192)
#define WOFF_GH  (WOFF_GR + 8192)
#define WOFF_VO  (WOFF_GH + 8192)
#define WOFF_W1  (WOFF_VO + 8192)
#define WTOT     (WOFF_W1 + 4096)
__device__ u32 g_whi[WTOT], g_wlo[WTOT];

// scalars: 0 ntmin 1 ntmax
// 2 bin1A 3 rankA  4 bin1B 5 rankB
// 6 bin2A 7 rankA2 8 bin2B 9 rankB2
// 10 med_bits
// 12 bin3A 13 -    14 bin3B 15 -
__device__ u32 g_scal[16];

// ---------------- generic helpers ----------------
__device__ __forceinline__ float wsum(float v) {
    #pragma unroll
    for (int o = 16; o; o >>= 1) v += __shfl_xor_sync(0xffffffffu, v, o);
    return v;
}
__device__ __forceinline__ float qsum(float v) {   // sum over 4-lane group
    v += __shfl_xor_sync(0xffffffffu, v, 1);
    v += __shfl_xor_sync(0xffffffffu, v, 2);
    return v;
}
__device__ __forceinline__ float sigmoidf_(float x) { return 1.0f / (1.0f + expf(-x)); }
__device__ __forceinline__ u32 smem_u32(const void* p) {
    u32 a;
    asm("{ .reg .u64 t; cvta.to.shared.u64 t, %1; cvt.u32.u64 %0, t; }" : "=r"(a) : "l"(p));
    return a;
}
// round-to-nearest split (used for weights, done once)
__device__ __forceinline__ void split2(float v0, float v1, u32& hip, u32& lop) {
    __nv_bfloat16 h0 = __float2bfloat16(v0);
    __nv_bfloat16 h1 = __float2bfloat16(v1);
    __nv_bfloat16 g0 = __float2bfloat16(v0 - __bfloat162float(h0));
    __nv_bfloat16 g1 = __float2bfloat16(v1 - __bfloat162float(h1));
    hip = ((u32)__bfloat16_as_ushort(h1) << 16) | (u32)__bfloat16_as_ushort(h0);
    lop = ((u32)__bfloat16_as_ushort(g1) << 16) | (u32)__bfloat16_as_ushort(g0);
}
// truncating split (cheap; dropped term ~2^-16, still 60x under tolerance)
__device__ __forceinline__ void split2t(float2 v, u32& hip, u32& lop) {
    u32 bx = __float_as_uint(v.x), by = __float_as_uint(v.y);
    hip = __byte_perm(bx, by, 0x7632);
    float l0 = v.x - __uint_as_float(bx & 0xFFFF0000u);
    float l1 = v.y - __uint_as_float(by & 0xFFFF0000u);
    lop = __byte_perm(__float_as_uint(l0), __float_as_uint(l1), 0x7632);
}

// mma.sync m16n8k16 row.col f32 <- bf16 x bf16 + f32   (baseline sm_80+ PTX)
__device__ __forceinline__ void mma16816(float* d, const u32* a, const u32* b) {
    asm volatile(
        "mma.sync.aligned.m16n8k16.row.col.f32.bf16.bf16.f32 "
        "{%0,%1,%2,%3}, {%4,%5,%6,%7}, {%8,%9}, {%0,%1,%2,%3};"
        : "+f"(d[0]), "+f"(d[1]), "+f"(d[2]), "+f"(d[3])
        : "r"(a[0]), "r"(a[1]), "r"(a[2]), "r"(a[3]), "r"(b[0]), "r"(b[1]));
}
__device__ __forceinline__ void ldsm4(u32* r, u32 addr) {
    asm volatile("ldmatrix.sync.aligned.m8n8.x4.shared.b16 {%0,%1,%2,%3}, [%4];"
                 : "=r"(r[0]), "=r"(r[1]), "=r"(r[2]), "=r"(r[3]) : "r"(addr));
}

// ---------------- attention weight composition: Wc = Wo @ Wv ----------------
__global__ void k_compose(const float* __restrict__ Wv, const float* __restrict__ Wo,
                          const float* __restrict__ bv, const float* __restrict__ bo,
                          float* __restrict__ Wc, float* __restrict__ bc) {
    __shared__ float srow[H];
    int j = blockIdx.x, t = threadIdx.x;
    srow[t] = Wo[j * H + t];
    __syncthreads();
    float s = 0.0f;
    #pragma unroll 8
    for (int q = 0; q < H; q++) s = fmaf(srow[q], Wv[q * H + t], s);
    Wc[j * H + t] = s;
    if (t == 0) {
        float b = bo[j];
        for (int q = 0; q < H; q++) b = fmaf(srow[q], bv[q], b);
        bc[j] = b;
    }
}

// ---------------- weight pre-conversion ----------------
struct WC {
    const float* src[12];
    int K[12], stride[12], end[12];
    int total;
};

__global__ void k_wconv(WC wc, u32* __restrict__ whi, u32* __restrict__ wlo) {
    int gi = blockIdx.x * blockDim.x + threadIdx.x;
    int gs = gridDim.x * blockDim.x;
    for (; gi < wc.total; gi += gs) {
        int m = 0;
        #pragma unroll
        for (int q = 0; q < 11; q++) if (gi >= wc.end[m]) m++;
        int base = m ? wc.end[m - 1] : 0;
        int local = gi - base;
        int st = wc.stride[m];
        int row = local / st, cp = local - row * st;
        int k = cp * 2, K = wc.K[m];
        const float* s = wc.src[m] + (size_t)row * K;
        float v0 = (k < K) ? s[k] : 0.0f;
        float v1 = (k + 1 < K) ? s[k + 1] : 0.0f;
        u32 hip, lop;
        split2(v0, v1, hip, lop);
        whi[gi] = hip; wlo[gi] = lop;
    }
}

// ---------------- init ----------------
__global__ void k_init(int N) {
    int tid = blockIdx.x * blockDim.x + threadIdx.x;
    int stride = gridDim.x * blockDim.x;
    for (int i = tid; i < N; i += stride) {
        g_nt[i] = 0.0f; g_upd[i] = 0; g_degrec[i] = 0; g_deghis[i] = 0;
    }
    for (int i = tid; i < 4096; i += stride) {
        g_hist1[i] = 0; g_hist2a[i] = 0; g_hist2b[i] = 0;
        if (i < 256) { g_hist3a[i] = 0; g_hist3b[i] = 0; }
    }
    if (tid == 0) { g_scal[0] = 0x7F800000u; g_scal[1] = 0u; }
}

// ---------------- edge pass 1: nt max, upd flags, L1 hist ----------------
__global__ void k_edge1(const int* __restrict__ ei, const float* __restrict__ ts, int E) {
    __shared__ u32 sh[4096];
    int tid = threadIdx.x;
    for (int i = tid; i < 4096; i += 256) sh[i] = 0;
    __syncthreads();
    int T = gridDim.x * blockDim.x;
    int g0 = blockIdx.x * blockDim.x + tid;
    int nfull = E / T;
    for (int it = 0; it < nfull; it++) {
        int e = g0 + it * T;
        int r = ei[e], c = ei[E + e];
        u32 tb = __float_as_uint(ts[e]);
        atomicMax((u32*)&g_nt[c], tb);   // ts >= 0 so bit order == float order
        g_upd[r] = 1; g_upd[c] = 1;
        u32 bin = tb >> 20;
        u32 mask = __match_any_sync(0xffffffffu, bin);
        if ((u32)(tid & 31) == (u32)(__ffs(mask) - 1))
            atomicAdd(&sh[bin], (u32)__popc(mask));
    }
    int e = g0 + nfull * T;
    bool valid = e < E;
    u32 am = __ballot_sync(0xffffffffu, valid);
    if (valid) {
        int r = ei[e], c = ei[E + e];
        u32 tb = __float_as_uint(ts[e]);
        atomicMax((u32*)&g_nt[c], tb);
        g_upd[r] = 1; g_upd[c] = 1;
        u32 bin = tb >> 20;
        u32 mask = __match_any_sync(am, bin);
        if ((u32)(tid & 31) == (u32)(__ffs(mask) - 1))
            atomicAdd(&sh[bin], (u32)__popc(mask));
    }
    __syncthreads();
    for (int i = tid; i < 4096; i += 256) {
        u32 v = sh[i];
        if (v) atomicAdd(&g_hist1[i], v);
    }
}

// ---------------- L2 hist pass (conditional on L1 bins) ----------------
__global__ void k_hl2(const float* __restrict__ ts, int E) {
    __shared__ u32 sa[4096], sb[4096];
    int tid = threadIdx.x;
    for (int i = tid; i < 4096; i += 256) { sa[i] = 0; sb[i] = 0; }
    __syncthreads();
    u32 binA = g_scal[2], binB = g_scal[4];
    int gs = gridDim.x * blockDim.x;
    for (int e = blockIdx.x * blockDim.x + tid; e < E; e += gs) {
        u32 tb = __float_as_uint(ts[e]);
        u32 b1 = tb >> 20, b2 = (tb >> 8) & 0xFFFu;
        if (b1 == binA) atomicAdd(&sa[b2], 1u);
        if (b1 == binB) atomicAdd(&sb[b2], 1u);
    }
    __syncthreads();
    for (int i = tid; i < 4096; i += 256) {
        u32 va = sa[i]; if (va) atomicAdd(&g_hist2a[i], va);
        u32 vb = sb[i]; if (vb) atomicAdd(&g_hist2b[i], vb);
    }
}

// ---------------- L3 hist pass ----------------
__global__ void k_hl3(const float* __restrict__ ts, int E) {
    __shared__ u32 sa[256], sb[256];
    int tid = threadIdx.x;
    if (tid < 256) { sa[tid] = 0; sb[tid] = 0; }
    __syncthreads();
    u32 pA = (g_scal[2] << 12) | g_scal[6];
    u32 pB = (g_scal[4] << 12) | g_scal[8];
    int gs = gridDim.x * blockDim.x;
    for (int e = blockIdx.x * blockDim.x + tid; e < E; e += gs) {
        u32 tb = __float_as_uint(ts[e]);
        u32 hi = tb >> 8, b3 = tb & 0xFFu;
        if (hi == pA) atomicAdd(&sa[b3], 1u);
        if (hi == pB) atomicAdd(&sb[b3], 1u);
    }
    __syncthreads();
    if (tid < 256) {
        u32 va = sa[tid]; if (va) atomicAdd(&g_hist3a[tid], va);
        u32 vb = sb[tid]; if (vb) atomicAdd(&g_hist3b[tid], vb);
    }
}

// ---------------- dual k-th select (block 0 -> A, block 1 -> B) -----------
__global__ void k_sel2(const u32* __restrict__ histA, const u32* __restrict__ histB,
                       int per,
                       u32 kA_imm, int kA_idx, int oA,
                       u32 kB_imm, int kB_idx, int oB) {
    __shared__ u32 sh[256];
    __shared__ u32 s_t;
    const u32* hist = blockIdx.x ? histB : histA;
    u32 k_imm = blockIdx.x ? kB_imm : kA_imm;
    int kidx = blockIdx.x ? kB_idx : kA_idx;
    int oidx = blockIdx.x ? oB : oA;
    int t = threadIdx.x;
    u32 k = (kidx >= 0) ? g_scal[kidx] : k_imm;
    u32 s = 0;
    for (int j = 0; j < per; j++) s += hist[t * per + j];
    u32 x = s;
    sh[t] = x; __syncthreads();
    for (int off = 1; off < 256; off <<= 1) {
        u32 a = (t >= off) ? sh[t - off] : 0u;
        __syncthreads();
        x += a; sh[t] = x;
        __syncthreads();
    }
    if (k < x && k >= x - s) s_t = (u32)t;
    __syncthreads();
    if ((u32)t == s_t) {
        u32 run = x - s;
        for (int j = 0; j < per; j++) {
            u32 hv = hist[t * per + j];
            if (k < run + hv) { g_scal[oidx] = (u32)(t * per + j); g_scal[oidx + 1] = k - run; break; }
            run += hv;
        }
    }
}

// ---------------- reconstruct median from 3-level bins ----------------
__global__ void k_med3() {
    u32 v0 = (g_scal[2] << 20) | (g_scal[6] << 8) | g_scal[12];
    u32 v1 = (g_scal[4] << 20) | (g_scal[8] << 8) | g_scal[14];
    g_scal[10] = __float_as_uint(0.5f * (__uint_as_float(v0) + __uint_as_float(v1)));
}

// ---------------- min/max over nt ----------------
__global__ void k_minmax(int N) {
    int tid = blockIdx.x * blockDim.x + threadIdx.x;
    int stride = gridDim.x * blockDim.x;
    u32 mn = 0x7F800000u, mx = 0u;
    for (int i = tid; i < N; i += stride) {
        u32 b = __float_as_uint(g_nt[i]);
        mn = min(mn, b); mx = max(mx, b);
    }
    #pragma unroll
    for (int o = 16; o; o >>= 1) {
        mn = min(mn, __shfl_xor_sync(0xffffffffu, mn, o));
        mx = max(mx, __shfl_xor_sync(0xffffffffu, mx, o));
    }
    if ((threadIdx.x & 31) == 0) {
        atomicMin(&g_scal[0], mn);
        atomicMax(&g_scal[1], mx);
    }
}

// ---------------- per-path in-degree ----------------
__global__ void k_deg(const int* __restrict__ ei, const float* __restrict__ ts, int E) {
    int e = blockIdx.x * blockDim.x + threadIdx.x;
    if (e >= E) return;
    float med = __uint_as_float(g_scal[10]);
    int c = ei[E + e];
    if (ts[e] >= med) atomicAdd(&g_degrec[c], 1u);
    else atomicAdd(&g_deghis[c], 1u);
}

// ---------------- CSR build ----------------
__global__ void k_scan1(int N) {
    __shared__ u32 sh[1024];
    int t = threadIdx.x;
    int i = blockIdx.x * 1024 + t;
    u32 v = (i < N) ? (g_degrec[i] + g_deghis[i]) : 0u;
    sh[t] = v;
    __syncthreads();
    for (int off = 1; off < 1024; off <<= 1) {
        u32 a = (t >= off) ? sh[t - off] : 0u;
        __syncthreads();
        sh[t] += a;
        __syncthreads();
    }
    if (i < N) g_offs[i] = sh[t];
    if (t == 1023) g_bsum[blockIdx.x] = sh[1023];
}

__global__ void k_scan2(int NB) {
    if (threadIdx.x == 0) {
        u32 run = 0;
        for (int b = 0; b < NB; b++) { u32 t2 = g_bsum[b]; g_bsum[b] = run; run += t2; }
    }
}

__global__ void k_scan3(int N) {
    int i = blockIdx.x * blockDim.x + threadIdx.x;
    if (i >= N) return;
    u32 cr = g_degrec[i], ch = g_deghis[i];
    u32 excl = g_offs[i] - (cr + ch) + g_bsum[i >> 10];
    g_offs[i] = excl;
    g_cursor[i] = excl;
    g_disrec[i] = rsqrtf((float)cr + 1.0f);
    g_dishis[i] = rsqrtf((float)ch + 1.0f);
}

__global__ void k_fill(const int* __restrict__ ei, const float* __restrict__ ts, int E) {
    int e = blockIdx.x * blockDim.x + threadIdx.x;
    if (e >= E) return;
    float med = __uint_as_float(g_scal[10]);
    int r = ei[e], c = ei[E + e];
    bool rec = ts[e] >= med;
    float coef = rec ? (g_disrec[r] * g_disrec[c]) : (g_dishis[r] * g_dishis[c]);
    u32 p = atomicAdd(&g_cursor[c], 1u);
    g_esrc[p] = ((u32)r << 1) | (rec ? 1u : 0u);
    g_ecoef[p] = coef;
}

// ================= HMMA split-bf16 GEMM ====================================
// C[i,j] = epi( sum_k A[i,k]*W[j,k] (+ A2[i,k]*W2[j,k]) )
struct Epi {
    const float* bias;
    const float* bias2;
    const float* wtime;
    const float* ex1;
    const float* ex2;
    const float* ex3;
    const float* mem;
    const unsigned char* upd;
    const float* nt;
};

// smem: 4 tiles [128 rows][72 bf16] (stride 144 B; conflict-free ldmatrix rows)
#define TSTR 144
#define AHI_OFF 0
#define ALO_OFF 18432
#define WHI_OFF 36864
#define WLO_OFF 55296
#define SMEMSZ  73728

// stage one [128 rows][64] f32 A-chunk into hi/lo bf16 tiles (truncating split)
__device__ __forceinline__ void stageA(const float* __restrict__ src, int nrows_valid,
                                       int row0, int Ksrc, int kbase,
                                       char* smem, int tid) {
    for (int idx = tid; idx < 128 * 32; idx += 256) {
        int r = idx >> 5, cp = idx & 31;
        int k = kbase + cp * 2;
        float2 v = make_float2(0.0f, 0.0f);
        int gr = row0 + r;
        if (gr < nrows_valid) {
            if (k + 1 < Ksrc) v = *(const float2*)(src + (size_t)gr * Ksrc + k);
            else if (k < Ksrc) v.x = src[(size_t)gr * Ksrc + k];
        }
        u32 hip, lop;
        split2t(v, hip, lop);
        int off = r * TSTR + cp * 4;
        *(u32*)(smem + AHI_OFF + off) = hip;
        *(u32*)(smem + ALO_OFF + off) = lop;
    }
}

template <int NOUT, int MODE>
__device__ __forceinline__ void epi2(int i, int c, float v0, float v1,
                                     const Epi& ep, float ntn, float* __restrict__ C) {
    if (MODE == 1) {
        v0 += ep.bias[c]; v1 += ep.bias[c + 1];
    } else if (MODE == 3) {
        v0 = sigmoidf_(v0 + ep.bias[c] + ep.bias2[c]);
        v1 = sigmoidf_(v1 + ep.bias[c + 1] + ep.bias2[c + 1]);
    } else if (MODE == 4) {
        float2 m2 = *(const float2*)&ep.mem[(size_t)i * NOUT + c];
        v0 = fmaxf(v0 + ep.bias[c] + ntn * ep.wtime[c] + ep.bias2[c], 0.0f) + m2.x;
        v1 = fmaxf(v1 + ep.bias[c + 1] + ntn * ep.wtime[c + 1] + ep.bias2[c + 1], 0.0f) + m2.y;
    } else if (MODE == 5) {
        float2 hc2 = *(const float2*)&ep.ex1[(size_t)i * NOUT + c];
        float2 r2  = *(const float2*)&ep.ex2[(size_t)i * NOUT + c];
        float2 z2  = *(const float2*)&ep.ex3[(size_t)i * NOUT + c];
        float2 m2  = *(const float2*)&ep.mem[(size_t)i * NOUT + c];
        bool u = ep.upd[i] != 0;
        float cc0 = tanhf(v0 + ep.bias[c] + r2.x * hc2.x);
        float cc1 = tanhf(v1 + ep.bias[c + 1] + r2.y * hc2.y);
        v0 = u ? (1.0f - z2.x) * cc0 + z2.x * m2.x : m2.x;
        v1 = u ? (1.0f - z2.y) * cc1 + z2.y * m2.y : m2.y;
    }
    *(float2*)&C[(size_t)i * NOUT + c] = make_float2(v0, v1);
}

template <int KSRC, int NOUT, int MODE, bool DUAL>
__global__ void __launch_bounds__(256)
k_tgemm(const float* __restrict__ A, u32 woff,
        const float* __restrict__ A2, u32 woff2,
        const u32* __restrict__ whi, const u32* __restrict__ wlo,
        int N, Epi ep, float* __restrict__ C) {
    extern __shared__ char smem[];
    const u32 sbase = smem_u32(smem);
    const int tid = threadIdx.x;
    const int wid = tid >> 5, lane = tid & 31;
    const int row0 = blockIdx.x * 128;
    constexpr int NCH = (KSRC + 63) / 64;
    constexpr int STRU = NCH * 32;
    constexpr int NT = NOUT / 8;
    const int laneg = lane >> 2, kq = (lane & 3) * 2;

    float acc[NT][4];
    #pragma unroll
    for (int n = 0; n < NT; n++)
        #pragma unroll
        for (int q = 0; q < 4; q++) acc[n][q] = 0.0f;

    // ldmatrix row-address offsets for this lane
    const u32 aoff = (u32)((wid * 16 + (lane & 15)) * TSTR + ((lane >> 4) << 4));
    const u32 boff0 = (u32)(((((lane >> 4) & 1) * 8) + (lane & 7)) * TSTR + (((lane >> 3) & 1) << 4));

    #pragma unroll
    for (int pass = 0; pass < (DUAL ? 2 : 1); pass++) {
        const float* Ap = pass ? A2 : A;
        const u32 wo = pass ? woff2 : woff;
        for (int ch = 0; ch < NCH; ch++) {
            if (pass || ch) __syncthreads();
            stageA(Ap, N, row0, KSRC, ch * 64, smem, tid);
            for (int idx = tid; idx < NOUT * 8; idx += 256) {
                int r2 = idx >> 3, q = idx & 7;
                size_t gs = (size_t)wo + (size_t)r2 * STRU + ch * 32 + q * 4;
                uint4 hv = *(const uint4*)(whi + gs);
                uint4 lv = *(const uint4*)(wlo + gs);
                *(uint4*)(smem + WHI_OFF + r2 * TSTR + q * 16) = hv;
                *(uint4*)(smem + WLO_OFF + r2 * TSTR + q * 16) = lv;
            }
            __syncthreads();
            #pragma unroll
            for (int kt = 0; kt < 4; kt++) {
                u32 ko = (u32)(kt * 32);
                u32 ah[4], al[4];
                ldsm4(ah, sbase + AHI_OFF + aoff + ko);
                ldsm4(al, sbase + ALO_OFF + aoff + ko);
                #pragma unroll
                for (int j = 0; j < NT / 2; j++) {
                    u32 bh[4], bl4[4];
                    u32 bo = boff0 + (u32)(j * 16 * TSTR) + ko;
                    ldsm4(bh, sbase + WHI_OFF + bo);
                    ldsm4(bl4, sbase + WLO_OFF + bo);
                    mma16816(acc[2 * j], ah, bh);
                    mma16816(acc[2 * j], ah, bl4);
                    mma16816(acc[2 * j], al, bh);
                    mma16816(acc[2 * j + 1], ah, bh + 2);
                    mma16816(acc[2 * j + 1], ah, bl4 + 2);
                    mma16816(acc[2 * j + 1], al, bh + 2);
                }
            }
        }
    }

    // ---- epilogue ----
    int i0 = row0 + wid * 16 + laneg;
    int i1 = i0 + 8;

    if (MODE == 7) {
        // classifier: relu(acc + b1) then dot with W2 (ex1), bias2 = b2 -> C = logits[N][2]
        float d00 = 0, d10 = 0, d01 = 0, d11 = 0;
        #pragma unroll
        for (int nt = 0; nt < NT; nt++) {
            int c = nt * 8 + kq;
            float w20 = ep.ex1[c], w21 = ep.ex1[c + 1];
            float w30 = ep.ex1[64 + c], w31 = ep.ex1[64 + c + 1];
            float b0 = ep.bias[c], b1v = ep.bias[c + 1];
            float v0 = fmaxf(acc[nt][0] + b0, 0.0f);
            float v1 = fmaxf(acc[nt][1] + b1v, 0.0f);
            d00 += v0 * w20 + v1 * w21;
            d10 += v0 * w30 + v1 * w31;
            v0 = fmaxf(acc[nt][2] + b0, 0.0f);
            v1 = fmaxf(acc[nt][3] + b1v, 0.0f);
            d01 += v0 * w20 + v1 * w21;
            d11 += v0 * w30 + v1 * w31;
        }
        d00 = qsum(d00); d10 = qsum(d10); d01 = qsum(d01); d11 = qsum(d11);
        if ((lane & 3) == 0) {
            float b20 = ep.bias2[0], b21 = ep.bias2[1];
            if (i0 < N) { C[(size_t)i0 * 2] = d00 + b20; C[(size_t)i0 * 2 + 1] = d10 + b21; }
            if (i1 < N) { C[(size_t)i1 * 2] = d01 + b20; C[(size_t)i1 * 2 + 1] = d11 + b21; }
        }
    } else if (MODE == 8) {
        // v = acc + bc + h2 residual; LayerNorm over row; C = h3
        float s0 = 0.0f, s1 = 0.0f;
        #pragma unroll
        for (int nt = 0; nt < NT; nt++) {
            int c = nt * 8 + kq;
            float b0 = ep.bias[c], b1v = ep.bias[c + 1];
            float2 e0 = (i0 < N) ? *(const float2*)&ep.ex1[(size_t)i0 * NOUT + c] : make_float2(0, 0);
            float2 e1 = (i1 < N) ? *(const float2*)&ep.ex1[(size_t)i1 * NOUT + c] : make_float2(0, 0);
            acc[nt][0] += b0 + e0.x;  acc[nt][1] += b1v + e0.y;
            acc[nt][2] += b0 + e1.x;  acc[nt][3] += b1v + e1.y;
            s0 += acc[nt][0] + acc[nt][1];
            s1 += acc[nt][2] + acc[nt][3];
        }
        float mean0 = qsum(s0) * (1.0f / H);
        float mean1 = qsum(s1) * (1.0f / H);
        float vs0 = 0.0f, vs1 = 0.0f;
        #pragma unroll
        for (int nt = 0; nt < NT; nt++) {
            float d;
            d = acc[nt][0] - mean0; vs0 += d * d;
            d = acc[nt][1] - mean0; vs0 += d * d;
            d = acc[nt][2] - mean1; vs1 += d * d;
            d = acc[nt][3] - mean1; vs1 += d * d;
        }
        float inv0 = rsqrtf(qsum(vs0) * (1.0f / H) + 1e-5f);
        float inv1 = rsqrtf(qsum(vs1) * (1.0f / H) + 1e-5f);
        #pragma unroll
        for (int nt = 0; nt < NT; nt++) {
            int c = nt * 8 + kq;
            float gv0 = ep.ex2[c], gv1 = ep.ex2[c + 1];
            float bv0 = ep.ex3[c], bv1 = ep.ex3[c + 1];
            if (i0 < N) {
                float o0 = (acc[nt][0] - mean0) * inv0 * gv0 + bv0;
                float o1 = (acc[nt][1] - mean0) * inv0 * gv1 + bv1;
                *(float2*)&C[(size_t)i0 * NOUT + c] = make_float2(o0, o1);
            }
            if (i1 < N) {
                float o0 = (acc[nt][2] - mean1) * inv1 * gv0 + bv0;
                float o1 = (acc[nt][3] - mean1) * inv1 * gv1 + bv1;
                *(float2*)&C[(size_t)i1 * NOUT + c] = make_float2(o0, o1);
            }
        }
    } else {
        float ntn0 = 0.0f, ntn1 = 0.0f;
        if (MODE == 4) {
            float tmin = __uint_as_float(g_scal[0]);
            float tmax = __uint_as_float(g_scal[1]);
            float inv = 1.0f / (tmax - tmin + 1e-8f);
            bool norm = tmax > tmin;
            if (i0 < N) { float t = ep.nt[i0]; ntn0 = norm ? (t - tmin) * inv : t; }
            if (i1 < N) { float t = ep.nt[i1]; ntn1 = norm ? (t - tmin) * inv : t; }
        }
        #pragma unroll
        for (int nt = 0; nt < NT; nt++) {
            int c = nt * 8 + kq;
            if (i0 < N) epi2<NOUT, MODE>(i0, c, acc[nt][0], acc[nt][1], ep, ntn0, C);
            if (i1 < N) epi2<NOUT, MODE>(i1, c, acc[nt][2], acc[nt][3], ep, ntn1, C);
        }
    }
}

// ---------------- fused GCN gather + path softmax mix + LayerNorm ---------
__global__ void k_gatherp(int N, const float* __restrict__ b_gr, const float* __restrict__ b_gh,
                          const float* __restrict__ lng, const float* __restrict__ lnb) {
    int gw = (blockIdx.x * blockDim.x + threadIdx.x) >> 5;
    int lane = threadIdx.x & 31;
    if (gw >= N) return;
    int i = gw;
    u32 start = g_offs[i];
    u32 cnt = g_degrec[i] + g_deghis[i];
    float4 ar = make_float4(0, 0, 0, 0), ah = make_float4(0, 0, 0, 0);
    for (u32 k = start; k < start + cnt; k++) {
        u32 pk = g_esrc[k];
        float cf = g_ecoef[k];
        int s = (int)(pk >> 1);
        if (pk & 1u) {
            float4 v = *(const float4*)&g_hlrec[(size_t)s * H + lane * 4];
            ar.x += v.x * cf; ar.y += v.y * cf; ar.z += v.z * cf; ar.w += v.w * cf;
        } else {
            float4 v = *(const float4*)&g_hlhis[(size_t)s * H + lane * 4];
            ah.x += v.x * cf; ah.y += v.y * cf; ah.z += v.z * cf; ah.w += v.w * cf;
        }
    }
    float fr = g_disrec[i] * g_disrec[i];
    float fh = g_dishis[i] * g_dishis[i];
    float4 sr = *(const float4*)&g_hlrec[(size_t)i * H + lane * 4];
    float4 sh = *(const float4*)&g_hlhis[(size_t)i * H + lane * 4];
    float4 br = *(const float4*)&b_gr[lane * 4];
    float4 bh = *(const float4*)&b_gh[lane * 4];
    float4 hr, hh;
    hr.x = ar.x + sr.x * fr + br.x; hr.y = ar.y + sr.y * fr + br.y;
    hr.z = ar.z + sr.z * fr + br.z; hr.w = ar.w + sr.w * fr + br.w;
    hh.x = ah.x + sh.x * fh + bh.x; hh.y = ah.y + sh.y * fh + bh.y;
    hh.z = ah.z + sh.z * fh + bh.z; hh.w = ah.w + sh.w * fh + bh.w;
    // path softmax mix + LN (fused)
    float s0 = wsum(hr.x + hr.y + hr.z + hr.w) * (1.0f / H);
    float s1 = wsum(hh.x + hh.y + hh.z + hh.w) * (1.0f / H);
    float m = fmaxf(s0, s1);
    float e0 = expf(s0 - m), e1 = expf(s1 - m);
    float w0 = e0 / (e0 + e1), w1 = e1 / (e0 + e1);
    float4 t;
    t.x = hr.x * w0 + hh.x * w1; t.y = hr.y * w0 + hh.y * w1;
    t.z = hr.z * w0 + hh.z * w1; t.w = hr.w * w0 + hh.w * w1;
    float mean = wsum(t.x + t.y + t.z + t.w) * (1.0f / H);
    float4 d;
    d.x = t.x - mean; d.y = t.y - mean; d.z = t.z - mean; d.w = t.w - mean;
    float var = wsum(d.x * d.x + d.y * d.y + d.z * d.z + d.w * d.w) * (1.0f / H);
    float inv = rsqrtf(var + 1e-5f);
    float4 gv = *(const float4*)&lng[lane * 4];
    float4 bv = *(const float4*)&lnb[lane * 4];
    float4 o;
    o.x = d.x * inv * gv.x + bv.x; o.y = d.y * inv * gv.y + bv.y;
    o.z = d.z * inv * gv.z + bv.z; o.w = d.w * inv * gv.w + bv.w;
    *(float4*)&g_h2[(size_t)i * H + lane * 4] = o;
}

// ---------------- host launcher ----------------
template <int KSRC, int NOUT, int MODE, bool DUAL>
static void tg(const float* A, u32 woff, const float* A2, u32 woff2,
               const u32* whi, const u32* wlo, int N, const Epi& ep, float* C) {
    cudaFuncSetAttribute(k_tgemm<KSRC, NOUT, MODE, DUAL>,
                         cudaFuncAttributeMaxDynamicSharedMemorySize, SMEMSZ);
    k_tgemm<KSRC, NOUT, MODE, DUAL><<<(N + 127) / 128, 256, SMEMSZ>>>(
        A, woff, A2, woff2, whi, wlo, N, ep, C);
}

extern "C" void kernel_launch(void* const* d_in, const int* in_sizes, int n_in,
                              void* d_out, int out_size) {
    const float* x       = (const float*)d_in[0];
    const int*   ei      = (const int*)d_in[1];
    const float* ts      = (const float*)d_in[2];
    const float* mem     = (const float*)d_in[3];
    const float* W_in    = (const float*)d_in[4];
    const float* b_in    = (const float*)d_in[5];
    const float* W_time  = (const float*)d_in[6];
    const float* b_time  = (const float*)d_in[7];
    const float* W_ih    = (const float*)d_in[8];
    const float* W_hh    = (const float*)d_in[9];
    const float* b_ih    = (const float*)d_in[10];
    const float* b_hh    = (const float*)d_in[11];
    const float* W_gr    = (const float*)d_in[12];
    const float* b_gr    = (const float*)d_in[13];
    const float* W_gh    = (const float*)d_in[14];
    const float* b_gh    = (const float*)d_in[15];
    const float* ln_pa_g = (const float*)d_in[16];
    const float* ln_pa_b = (const float*)d_in[17];
    const float* Wv      = (const float*)d_in[18];
    const float* bv      = (const float*)d_in[19];
    const float* Wo      = (const float*)d_in[20];
    const float* bo      = (const float*)d_in[21];
    const float* ln_at_g = (const float*)d_in[22];
    const float* ln_at_b = (const float*)d_in[23];
    const float* W1      = (const float*)d_in[24];
    const float* b1      = (const float*)d_in[25];
    const float* W2p     = (const float*)d_in[26];
    const float* b2      = (const float*)d_in[27];

    const int E = in_sizes[2];
    const int N = in_sizes[0] / F;
    float* out_logits = (float*)d_out;
    float* out_mem = (float*)d_out + (size_t)2 * N;

    float *p_h, *p_r, *p_z, *p_hc, *p_hlrec, *p_hlhis, *p_h2, *p_h3, *p_nt;
    float *p_wc, *p_bc;
    unsigned char* p_upd;
    u32 *p_h1, *p_h2a, *p_h2b, *p_h3a, *p_h3b, *p_whi, *p_wlo;
    cudaGetSymbolAddress((void**)&p_h, g_h);
    cudaGetSymbolAddress((void**)&p_r, g_r);
    cudaGetSymbolAddress((void**)&p_z, g_z);
    cudaGetSymbolAddress((void**)&p_hc, g_hc);
    cudaGetSymbolAddress((void**)&p_hlrec, g_hlrec);
    cudaGetSymbolAddress((void**)&p_hlhis, g_hlhis);
    cudaGetSymbolAddress((void**)&p_h2, g_h2);
    cudaGetSymbolAddress((void**)&p_h3, g_h3);
    cudaGetSymbolAddress((void**)&p_nt, g_nt);
    cudaGetSymbolAddress((void**)&p_upd, g_upd);
    cudaGetSymbolAddress((void**)&p_h1, g_hist1);
    cudaGetSymbolAddress((void**)&p_h2a, g_hist2a);
    cudaGetSymbolAddress((void**)&p_h2b, g_hist2b);
    cudaGetSymbolAddress((void**)&p_h3a, g_hist3a);
    cudaGetSymbolAddress((void**)&p_h3b, g_hist3b);
    cudaGetSymbolAddress((void**)&p_whi, g_whi);
    cudaGetSymbolAddress((void**)&p_wlo, g_wlo);
    cudaGetSymbolAddress((void**)&p_wc, g_wc);
    cudaGetSymbolAddress((void**)&p_bc, g_bc);

    const u32 k0 = (u32)((E - 1) / 2);
    const u32 k1 = (u32)(E / 2);
    const int EB = (E + 255) / 256;
    const int NB1024 = (N + 1023) / 1024;
    const int NWB = (N * 32 + 255) / 256;

    // weight conversion descriptor: 11 real entries (VO uses composed g_wc)
    WC wc;
    const float* wsrcs[11] = {W_in, W_ih, W_ih + H * H, W_ih + 2 * H * H,
                              W_hh, W_hh + H * H, W_hh + 2 * H * H,
                              W_gr, W_gh, p_wc, W1};
    int wK[11]    = {F, H, H, H, H, H, H, H, H, H, H};
    int wrows[11] = {H, H, H, H, H, H, H, H, H, H, 64};
    int run = 0;
    for (int m = 0; m < 11; m++) {
        wc.src[m] = wsrcs[m];
        wc.K[m] = wK[m];
        wc.stride[m] = ((wK[m] + 63) / 64) * 32;
        run += wrows[m] * wc.stride[m];
        wc.end[m] = run;
    }
    wc.src[11] = W1; wc.K[11] = H; wc.stride[11] = 64; wc.end[11] = run;
    wc.total = run;

    // ---- preprocessing ----
    k_init<<<256, 256>>>(N);                                       // 1
    k_compose<<<H, H>>>(Wv, Wo, bv, bo, p_wc, p_bc);               // 2
    k_wconv<<<128, 256>>>(wc, p_whi, p_wlo);                       // 3
    k_edge1<<<1184, 256>>>(ei, ts, E);                             // 4
    k_minmax<<<592, 256>>>(N);                                     // 5
    {
        Epi ep{}; ep.bias = b_hh + 2 * H;                          // 6
        tg<H, H, 1, false>(mem, WOFF_HHC, nullptr, 0, p_whi, p_wlo, N, ep, p_hc);
    }
    k_sel2<<<2, 256>>>(p_h1, p_h1, 16, k0, -1, 2, k1, -1, 4);
    k_hl2<<<888, 256>>>(ts, E);
    k_sel2<<<2, 256>>>(p_h2a, p_h2b, 16, 0, 3, 6, 0, 5, 8);
    k_hl3<<<888, 256>>>(ts, E);
    k_sel2<<<2, 256>>>(p_h3a, p_h3b, 1, 0, 7, 12, 0, 9, 14);
    k_med3<<<1, 1>>>();
    k_deg<<<EB, 256>>>(ei, ts, E);
    k_scan1<<<NB1024, 1024>>>(N);
    k_scan2<<<1, 1>>>(NB1024);
    k_scan3<<<(N + 255) / 256, 256>>>(N);
    k_fill<<<EB, 256>>>(ei, ts, E);

    // ---- h = relu(x@W_in^T + b_in + nt*W_time + b_time) + memory ----
    {
        Epi ep{}; ep.bias = b_in; ep.bias2 = b_time; ep.wtime = W_time; ep.mem = mem; ep.nt = p_nt;
        tg<F, H, 4, false>(x, WOFF_IN, nullptr, 0, p_whi, p_wlo, N, ep, p_h);
    }
    // ---- GRU gates ----
    {
        Epi ep{}; ep.bias = b_ih; ep.bias2 = b_hh;
        tg<H, H, 3, true>(p_h, WOFF_IHR, mem, WOFF_HHR, p_whi, p_wlo, N, ep, p_r);
    }
    {
        Epi ep{}; ep.bias = b_ih + H; ep.bias2 = b_hh + H;
        tg<H, H, 3, true>(p_h, WOFF_IHZ, mem, WOFF_HHZ, p_whi, p_wlo, N, ep, p_z);
    }
    {
        Epi ep{}; ep.bias = b_ih + 2 * H; ep.ex1 = p_hc; ep.ex2 = p_r; ep.ex3 = p_z;
        ep.mem = mem; ep.upd = p_upd;
        tg<H, H, 5, false>(p_h, WOFF_IHC, nullptr, 0, p_whi, p_wlo, N, ep, out_mem);
    }
    // ---- GCN linears + fused gather/pathagg ----
    {
        Epi ep{};
        tg<H, H, 0, false>(p_h, WOFF_GR, nullptr, 0, p_whi, p_wlo, N, ep, p_hlrec);
        tg<H, H, 0, false>(p_h, WOFF_GH, nullptr, 0, p_whi, p_wlo, N, ep, p_hlhis);
    }
    k_gatherp<<<NWB, 256>>>(N, b_gr, b_gh, ln_pa_g, ln_pa_b);
    // ---- attention composed GEMM + residual + LN fused -> h3 ----
    {
        Epi ep{}; ep.bias = p_bc; ep.ex1 = p_h2; ep.ex2 = ln_at_g; ep.ex3 = ln_at_b;
        tg<H, H, 8, false>(p_h2, WOFF_VO, nullptr, 0, p_whi, p_wlo, N, ep, p_h3);
    }
    // ---- classifier + logits fused ----
    {
        Epi ep{}; ep.bias = b1; ep.ex1 = W2p; ep.bias2 = b2;
        tg<H, 64, 7, false>(p_h3, WOFF_W1, nullptr, 0, p_whi, p_wlo, N, ep, out_logits);
    }
}

// round 17
// speedup vs baseline: 1.1368x; 1.0102x over previous
#include <cuda_runtime.h>
#include <cuda_bf16.h>

#define H 128
#define F 166
#define NMAX 100000
#define EMAX 600000

typedef unsigned int u32;
typedef unsigned long long u64;

// ---------------- scratch (static device memory; no allocs) ----------------
__device__ float g_h[(size_t)NMAX * H];
__device__ float g_r[(size_t)NMAX * H];
__device__ float g_z[(size_t)NMAX * H];
__device__ float g_hc[(size_t)NMAX * H];
__device__ float g_hlrec[(size_t)NMAX * H];
__device__ float g_hlhis[(size_t)NMAX * H];
__device__ float g_h2[(size_t)NMAX * H];
__device__ float g_h3[(size_t)NMAX * H];
__device__ float g_nt[NMAX];
__device__ u32 g_degrec[NMAX], g_deghis[NMAX];
__device__ float g_disrec[NMAX], g_dishis[NMAX];
__device__ unsigned char g_upd[NMAX];
// small histograms: L1 = tb>>20 (4096), L2 = (tb>>8)&0xFFF (4096), L3 = tb&0xFF (256)
__device__ u32 g_hist1[4096], g_hist2a[4096], g_hist2b[4096], g_hist3a[256], g_hist3b[256];
__device__ u32 g_offs[NMAX], g_cursor[NMAX], g_bsum[512];
__device__ u32 g_esrc[EMAX];
__device__ float g_ecoef[EMAX];
// composed attention weight Wc = Wo @ Wv and bias bc = Wo @ bv + bo
__device__ float g_wc[H * H];
__device__ float g_bc[H];

// pre-converted weights: packed bf16 pairs, hi and lo parts
#define WOFF_IN  0
#define WOFF_IHR 12288
#define WOFF_IHZ (WOFF_IHR + 8192)
#define WOFF_IHC (WOFF_IHZ + 8192)
#define WOFF_HHR (WOFF_IHC + 8192)
#define WOFF_HHZ (WOFF_HHR + 8192)
#define WOFF_HHC (WOFF_HHZ + 8192)
#define WOFF_GR  (WOFF_HHC + 8192)
#define WOFF_GH  (WOFF_GR + 8192)
#define WOFF_VO  (WOFF_GH + 8192)
#define WOFF_W1  (WOFF_VO + 8192)
#define WTOT     (WOFF_W1 + 4096)
__device__ u32 g_whi[WTOT], g_wlo[WTOT];

// scalars: 0 ntmin 1 ntmax
// 2 bin1A 3 rankA  4 bin1B 5 rankB
// 6 bin2A 7 rankA2 8 bin2B 9 rankB2
// 10 med_bits
// 12 bin3A 13 -    14 bin3B 15 -
__device__ u32 g_scal[16];

// ---------------- generic helpers ----------------
__device__ __forceinline__ float wsum(float v) {
    #pragma unroll
    for (int o = 16; o; o >>= 1) v += __shfl_xor_sync(0xffffffffu, v, o);
    return v;
}
__device__ __forceinline__ float qsum(float v) {   // sum over 4-lane group
    v += __shfl_xor_sync(0xffffffffu, v, 1);
    v += __shfl_xor_sync(0xffffffffu, v, 2);
    return v;
}
__device__ __forceinline__ float sigmoidf_(float x) { return 1.0f / (1.0f + expf(-x)); }
__device__ __forceinline__ u32 smem_u32(const void* p) {
    u32 a;
    asm("{ .reg .u64 t; cvta.to.shared.u64 t, %1; cvt.u32.u64 %0, t; }" : "=r"(a) : "l"(p));
    return a;
}
// round-to-nearest split (used for weights, done once)
__device__ __forceinline__ void split2(float v0, float v1, u32& hip, u32& lop) {
    __nv_bfloat16 h0 = __float2bfloat16(v0);
    __nv_bfloat16 h1 = __float2bfloat16(v1);
    __nv_bfloat16 g0 = __float2bfloat16(v0 - __bfloat162float(h0));
    __nv_bfloat16 g1 = __float2bfloat16(v1 - __bfloat162float(h1));
    hip = ((u32)__bfloat16_as_ushort(h1) << 16) | (u32)__bfloat16_as_ushort(h0);
    lop = ((u32)__bfloat16_as_ushort(g1) << 16) | (u32)__bfloat16_as_ushort(g0);
}
// truncating split (cheap; dropped term ~2^-16, still 60x under tolerance)
__device__ __forceinline__ void split2t(float2 v, u32& hip, u32& lop) {
    u32 bx = __float_as_uint(v.x), by = __float_as_uint(v.y);
    hip = __byte_perm(bx, by, 0x7632);
    float l0 = v.x - __uint_as_float(bx & 0xFFFF0000u);
    float l1 = v.y - __uint_as_float(by & 0xFFFF0000u);
    lop = __byte_perm(__float_as_uint(l0), __float_as_uint(l1), 0x7632);
}

// mma.sync m16n8k16 row.col f32 <- bf16 x bf16 + f32   (baseline sm_80+ PTX)
__device__ __forceinline__ void mma16816(float* d, const u32* a, const u32* b) {
    asm volatile(
        "mma.sync.aligned.m16n8k16.row.col.f32.bf16.bf16.f32 "
        "{%0,%1,%2,%3}, {%4,%5,%6,%7}, {%8,%9}, {%0,%1,%2,%3};"
        : "+f"(d[0]), "+f"(d[1]), "+f"(d[2]), "+f"(d[3])
        : "r"(a[0]), "r"(a[1]), "r"(a[2]), "r"(a[3]), "r"(b[0]), "r"(b[1]));
}
__device__ __forceinline__ void ldsm4(u32* r, u32 addr) {
    asm volatile("ldmatrix.sync.aligned.m8n8.x4.shared.b16 {%0,%1,%2,%3}, [%4];"
                 : "=r"(r[0]), "=r"(r[1]), "=r"(r[2]), "=r"(r[3]) : "r"(addr));
}

// ---------------- attention weight composition: Wc = Wo @ Wv ----------------
__global__ void k_compose(const float* __restrict__ Wv, const float* __restrict__ Wo,
                          const float* __restrict__ bv, const float* __restrict__ bo,
                          float* __restrict__ Wc, float* __restrict__ bc) {
    __shared__ float srow[H];
    int j = blockIdx.x, t = threadIdx.x;
    srow[t] = Wo[j * H + t];
    __syncthreads();
    float s = 0.0f;
    #pragma unroll 8
    for (int q = 0; q < H; q++) s = fmaf(srow[q], Wv[q * H + t], s);
    Wc[j * H + t] = s;
    if (t == 0) {
        float b = bo[j];
        for (int q = 0; q < H; q++) b = fmaf(srow[q], bv[q], b);
        bc[j] = b;
    }
}

// ---------------- weight pre-conversion ----------------
struct WC {
    const float* src[12];
    int K[12], stride[12], end[12];
    int total;
};

__global__ void k_wconv(WC wc, u32* __restrict__ whi, u32* __restrict__ wlo) {
    int gi = blockIdx.x * blockDim.x + threadIdx.x;
    int gs = gridDim.x * blockDim.x;
    for (; gi < wc.total; gi += gs) {
        int m = 0;
        #pragma unroll
        for (int q = 0; q < 11; q++) if (gi >= wc.end[m]) m++;
        int base = m ? wc.end[m - 1] : 0;
        int local = gi - base;
        int st = wc.stride[m];
        int row = local / st, cp = local - row * st;
        int k = cp * 2, K = wc.K[m];
        const float* s = wc.src[m] + (size_t)row * K;
        float v0 = (k < K) ? s[k] : 0.0f;
        float v1 = (k + 1 < K) ? s[k + 1] : 0.0f;
        u32 hip, lop;
        split2(v0, v1, hip, lop);
        whi[gi] = hip; wlo[gi] = lop;
    }
}

// ---------------- init ----------------
__global__ void k_init(int N) {
    int tid = blockIdx.x * blockDim.x + threadIdx.x;
    int stride = gridDim.x * blockDim.x;
    for (int i = tid; i < N; i += stride) {
        g_nt[i] = 0.0f; g_upd[i] = 0; g_degrec[i] = 0; g_deghis[i] = 0;
    }
    for (int i = tid; i < 4096; i += stride) {
        g_hist1[i] = 0; g_hist2a[i] = 0; g_hist2b[i] = 0;
        if (i < 256) { g_hist3a[i] = 0; g_hist3b[i] = 0; }
    }
    if (tid == 0) { g_scal[0] = 0x7F800000u; g_scal[1] = 0u; }
}

// ---------------- edge pass 1: nt max, upd flags, L1 hist ----------------
__global__ void k_edge1(const int* __restrict__ ei, const float* __restrict__ ts, int E) {
    __shared__ u32 sh[4096];
    int tid = threadIdx.x;
    for (int i = tid; i < 4096; i += 256) sh[i] = 0;
    __syncthreads();
    int T = gridDim.x * blockDim.x;
    int g0 = blockIdx.x * blockDim.x + tid;
    int nfull = E / T;
    for (int it = 0; it < nfull; it++) {
        int e = g0 + it * T;
        int r = ei[e], c = ei[E + e];
        u32 tb = __float_as_uint(ts[e]);
        atomicMax((u32*)&g_nt[c], tb);   // ts >= 0 so bit order == float order
        g_upd[r] = 1; g_upd[c] = 1;
        u32 bin = tb >> 20;
        u32 mask = __match_any_sync(0xffffffffu, bin);
        if ((u32)(tid & 31) == (u32)(__ffs(mask) - 1))
            atomicAdd(&sh[bin], (u32)__popc(mask));
    }
    int e = g0 + nfull * T;
    bool valid = e < E;
    u32 am = __ballot_sync(0xffffffffu, valid);
    if (valid) {
        int r = ei[e], c = ei[E + e];
        u32 tb = __float_as_uint(ts[e]);
        atomicMax((u32*)&g_nt[c], tb);
        g_upd[r] = 1; g_upd[c] = 1;
        u32 bin = tb >> 20;
        u32 mask = __match_any_sync(am, bin);
        if ((u32)(tid & 31) == (u32)(__ffs(mask) - 1))
            atomicAdd(&sh[bin], (u32)__popc(mask));
    }
    __syncthreads();
    for (int i = tid; i < 4096; i += 256) {
        u32 v = sh[i];
        if (v) atomicAdd(&g_hist1[i], v);
    }
}

// ---------------- L2 hist pass (conditional on L1 bins) ----------------
__global__ void k_hl2(const float* __restrict__ ts, int E) {
    __shared__ u32 sa[4096], sb[4096];
    int tid = threadIdx.x;
    for (int i = tid; i < 4096; i += 256) { sa[i] = 0; sb[i] = 0; }
    __syncthreads();
    u32 binA = g_scal[2], binB = g_scal[4];
    int gs = gridDim.x * blockDim.x;
    for (int e = blockIdx.x * blockDim.x + tid; e < E; e += gs) {
        u32 tb = __float_as_uint(ts[e]);
        u32 b1 = tb >> 20, b2 = (tb >> 8) & 0xFFFu;
        if (b1 == binA) atomicAdd(&sa[b2], 1u);
        if (b1 == binB) atomicAdd(&sb[b2], 1u);
    }
    __syncthreads();
    for (int i = tid; i < 4096; i += 256) {
        u32 va = sa[i]; if (va) atomicAdd(&g_hist2a[i], va);
        u32 vb = sb[i]; if (vb) atomicAdd(&g_hist2b[i], vb);
    }
}

// ---------------- L3 hist pass ----------------
__global__ void k_hl3(const float* __restrict__ ts, int E) {
    __shared__ u32 sa[256], sb[256];
    int tid = threadIdx.x;
    if (tid < 256) { sa[tid] = 0; sb[tid] = 0; }
    __syncthreads();
    u32 pA = (g_scal[2] << 12) | g_scal[6];
    u32 pB = (g_scal[4] << 12) | g_scal[8];
    int gs = gridDim.x * blockDim.x;
    for (int e = blockIdx.x * blockDim.x + tid; e < E; e += gs) {
        u32 tb = __float_as_uint(ts[e]);
        u32 hi = tb >> 8, b3 = tb & 0xFFu;
        if (hi == pA) atomicAdd(&sa[b3], 1u);
        if (hi == pB) atomicAdd(&sb[b3], 1u);
    }
    __syncthreads();
    if (tid < 256) {
        u32 va = sa[tid]; if (va) atomicAdd(&g_hist3a[tid], va);
        u32 vb = sb[tid]; if (vb) atomicAdd(&g_hist3b[tid], vb);
    }
}

// ---------------- dual k-th select (block 0 -> A, block 1 -> B) -----------
__global__ void k_sel2(const u32* __restrict__ histA, const u32* __restrict__ histB,
                       int per,
                       u32 kA_imm, int kA_idx, int oA,
                       u32 kB_imm, int kB_idx, int oB) {
    __shared__ u32 sh[256];
    __shared__ u32 s_t;
    const u32* hist = blockIdx.x ? histB : histA;
    u32 k_imm = blockIdx.x ? kB_imm : kA_imm;
    int kidx = blockIdx.x ? kB_idx : kA_idx;
    int oidx = blockIdx.x ? oB : oA;
    int t = threadIdx.x;
    u32 k = (kidx >= 0) ? g_scal[kidx] : k_imm;
    u32 s = 0;
    for (int j = 0; j < per; j++) s += hist[t * per + j];
    u32 x = s;
    sh[t] = x; __syncthreads();
    for (int off = 1; off < 256; off <<= 1) {
        u32 a = (t >= off) ? sh[t - off] : 0u;
        __syncthreads();
        x += a; sh[t] = x;
        __syncthreads();
    }
    if (k < x && k >= x - s) s_t = (u32)t;
    __syncthreads();
    if ((u32)t == s_t) {
        u32 run = x - s;
        for (int j = 0; j < per; j++) {
            u32 hv = hist[t * per + j];
            if (k < run + hv) { g_scal[oidx] = (u32)(t * per + j); g_scal[oidx + 1] = k - run; break; }
            run += hv;
        }
    }
}

// ---------------- reconstruct median from 3-level bins ----------------
__global__ void k_med3() {
    u32 v0 = (g_scal[2] << 20) | (g_scal[6] << 8) | g_scal[12];
    u32 v1 = (g_scal[4] << 20) | (g_scal[8] << 8) | g_scal[14];
    g_scal[10] = __float_as_uint(0.5f * (__uint_as_float(v0) + __uint_as_float(v1)));
}

// ---------------- min/max over nt ----------------
__global__ void k_minmax(int N) {
    int tid = blockIdx.x * blockDim.x + threadIdx.x;
    int stride = gridDim.x * blockDim.x;
    u32 mn = 0x7F800000u, mx = 0u;
    for (int i = tid; i < N; i += stride) {
        u32 b = __float_as_uint(g_nt[i]);
        mn = min(mn, b); mx = max(mx, b);
    }
    #pragma unroll
    for (int o = 16; o; o >>= 1) {
        mn = min(mn, __shfl_xor_sync(0xffffffffu, mn, o));
        mx = max(mx, __shfl_xor_sync(0xffffffffu, mx, o));
    }
    if ((threadIdx.x & 31) == 0) {
        atomicMin(&g_scal[0], mn);
        atomicMax(&g_scal[1], mx);
    }
}

// ---------------- per-path in-degree ----------------
__global__ void k_deg(const int* __restrict__ ei, const float* __restrict__ ts, int E) {
    int e = blockIdx.x * blockDim.x + threadIdx.x;
    if (e >= E) return;
    float med = __uint_as_float(g_scal[10]);
    int c = ei[E + e];
    if (ts[e] >= med) atomicAdd(&g_degrec[c], 1u);
    else atomicAdd(&g_deghis[c], 1u);
}

// ---------------- CSR build ----------------
__global__ void k_scan1(int N) {
    __shared__ u32 sh[1024];
    int t = threadIdx.x;
    int i = blockIdx.x * 1024 + t;
    u32 v = (i < N) ? (g_degrec[i] + g_deghis[i]) : 0u;
    sh[t] = v;
    __syncthreads();
    for (int off = 1; off < 1024; off <<= 1) {
        u32 a = (t >= off) ? sh[t - off] : 0u;
        __syncthreads();
        sh[t] += a;
        __syncthreads();
    }
    if (i < N) g_offs[i] = sh[t];
    if (t == 1023) g_bsum[blockIdx.x] = sh[1023];
}

__global__ void k_scan2(int NB) {
    if (threadIdx.x == 0) {
        u32 run = 0;
        for (int b = 0; b < NB; b++) { u32 t2 = g_bsum[b]; g_bsum[b] = run; run += t2; }
    }
}

__global__ void k_scan3(int N) {
    int i = blockIdx.x * blockDim.x + threadIdx.x;
    if (i >= N) return;
    u32 cr = g_degrec[i], ch = g_deghis[i];
    u32 excl = g_offs[i] - (cr + ch) + g_bsum[i >> 10];
    g_offs[i] = excl;
    g_cursor[i] = excl;
    g_disrec[i] = rsqrtf((float)cr + 1.0f);
    g_dishis[i] = rsqrtf((float)ch + 1.0f);
}

__global__ void k_fill(const int* __restrict__ ei, const float* __restrict__ ts, int E) {
    int e = blockIdx.x * blockDim.x + threadIdx.x;
    if (e >= E) return;
    float med = __uint_as_float(g_scal[10]);
    int r = ei[e], c = ei[E + e];
    bool rec = ts[e] >= med;
    float coef = rec ? (g_disrec[r] * g_disrec[c]) : (g_dishis[r] * g_dishis[c]);
    u32 p = atomicAdd(&g_cursor[c], 1u);
    g_esrc[p] = ((u32)r << 1) | (rec ? 1u : 0u);
    g_ecoef[p] = coef;
}

// ================= HMMA split-bf16 GEMM ====================================
// C[i,j] = epi( sum_k A[i,k]*W[j,k] (+ A2[i,k]*W2[j,k]) )
struct Epi {
    const float* bias;
    const float* bias2;
    const float* wtime;
    const float* ex1;
    const float* ex2;
    const float* ex3;
    const float* mem;
    const unsigned char* upd;
    const float* nt;
};

// smem: 4 tiles [128 rows][72 bf16] (stride 144 B; conflict-free ldmatrix rows)
#define TSTR 144
#define AHI_OFF 0
#define ALO_OFF 18432
#define WHI_OFF 36864
#define WLO_OFF 55296
#define SMEMSZ  73728

// stage one [128 rows][64] f32 A-chunk into hi/lo bf16 tiles (truncating split)
// KSRC % 4 == 0: rows 16B-aligned -> float4 path. Otherwise float2 path.
template <int KSRC>
__device__ __forceinline__ void stageA(const float* __restrict__ src, int nrows_valid,
                                       int row0, int kbase,
                                       char* smem, int tid) {
    if (KSRC % 4 == 0) {
        for (int idx = tid; idx < 128 * 16; idx += 256) {
            int r = idx >> 4, cq = idx & 15;
            int k = kbase + cq * 4;
            float4 v = make_float4(0.0f, 0.0f, 0.0f, 0.0f);
            int gr = row0 + r;
            if (gr < nrows_valid) v = *(const float4*)(src + (size_t)gr * KSRC + k);
            u32 h0, l0, h1, l1;
            split2t(make_float2(v.x, v.y), h0, l0);
            split2t(make_float2(v.z, v.w), h1, l1);
            int off = r * TSTR + cq * 8;
            *(u64*)(smem + AHI_OFF + off) = ((u64)h1 << 32) | h0;
            *(u64*)(smem + ALO_OFF + off) = ((u64)l1 << 32) | l0;
        }
    } else {
        for (int idx = tid; idx < 128 * 32; idx += 256) {
            int r = idx >> 5, cp = idx & 31;
            int k = kbase + cp * 2;
            float2 v = make_float2(0.0f, 0.0f);
            int gr = row0 + r;
            if (gr < nrows_valid) {
                if (k + 1 < KSRC) v = *(const float2*)(src + (size_t)gr * KSRC + k);
                else if (k < KSRC) v.x = src[(size_t)gr * KSRC + k];
            }
            u32 hip, lop;
            split2t(v, hip, lop);
            int off = r * TSTR + cp * 4;
            *(u32*)(smem + AHI_OFF + off) = hip;
            *(u32*)(smem + ALO_OFF + off) = lop;
        }
    }
}

template <int NOUT, int MODE>
__device__ __forceinline__ void epi2(int i, int c, float v0, float v1,
                                     const Epi& ep, float ntn, float* __restrict__ C) {
    if (MODE == 1) {
        v0 += ep.bias[c]; v1 += ep.bias[c + 1];
    } else if (MODE == 3) {
        v0 = sigmoidf_(v0 + ep.bias[c] + ep.bias2[c]);
        v1 = sigmoidf_(v1 + ep.bias[c + 1] + ep.bias2[c + 1]);
    } else if (MODE == 4) {
        float2 m2 = *(const float2*)&ep.mem[(size_t)i * NOUT + c];
        v0 = fmaxf(v0 + ep.bias[c] + ntn * ep.wtime[c] + ep.bias2[c], 0.0f) + m2.x;
        v1 = fmaxf(v1 + ep.bias[c + 1] + ntn * ep.wtime[c + 1] + ep.bias2[c + 1], 0.0f) + m2.y;
    } else if (MODE == 5) {
        float2 hc2 = *(const float2*)&ep.ex1[(size_t)i * NOUT + c];
        float2 r2  = *(const float2*)&ep.ex2[(size_t)i * NOUT + c];
        float2 z2  = *(const float2*)&ep.ex3[(size_t)i * NOUT + c];
        float2 m2  = *(const float2*)&ep.mem[(size_t)i * NOUT + c];
        bool u = ep.upd[i] != 0;
        float cc0 = tanhf(v0 + ep.bias[c] + r2.x * hc2.x);
        float cc1 = tanhf(v1 + ep.bias[c + 1] + r2.y * hc2.y);
        v0 = u ? (1.0f - z2.x) * cc0 + z2.x * m2.x : m2.x;
        v1 = u ? (1.0f - z2.y) * cc1 + z2.y * m2.y : m2.y;
    }
    *(float2*)&C[(size_t)i * NOUT + c] = make_float2(v0, v1);
}

template <int KSRC, int NOUT, int MODE, bool DUAL>
__global__ void __launch_bounds__(256)
k_tgemm(const float* __restrict__ A, u32 woff,
        const float* __restrict__ A2, u32 woff2,
        const u32* __restrict__ whi, const u32* __restrict__ wlo,
        int N, Epi ep, float* __restrict__ C) {
    extern __shared__ char smem[];
    const u32 sbase = smem_u32(smem);
    const int tid = threadIdx.x;
    const int wid = tid >> 5, lane = tid & 31;
    const int row0 = blockIdx.x * 128;
    constexpr int NCH = (KSRC + 63) / 64;
    constexpr int STRU = NCH * 32;
    constexpr int NT = NOUT / 8;
    const int laneg = lane >> 2, kq = (lane & 3) * 2;

    float acc[NT][4];
    #pragma unroll
    for (int n = 0; n < NT; n++)
        #pragma unroll
        for (int q = 0; q < 4; q++) acc[n][q] = 0.0f;

    // ldmatrix row-address offsets for this lane
    const u32 aoff = (u32)((wid * 16 + (lane & 15)) * TSTR + ((lane >> 4) << 4));
    const u32 boff0 = (u32)(((((lane >> 4) & 1) * 8) + (lane & 7)) * TSTR + (((lane >> 3) & 1) << 4));

    #pragma unroll
    for (int pass = 0; pass < (DUAL ? 2 : 1); pass++) {
        const float* Ap = pass ? A2 : A;
        const u32 wo = pass ? woff2 : woff;
        for (int ch = 0; ch < NCH; ch++) {
            if (pass || ch) __syncthreads();
            stageA<KSRC>(Ap, N, row0, ch * 64, smem, tid);
            for (int idx = tid; idx < NOUT * 8; idx += 256) {
                int r2 = idx >> 3, q = idx & 7;
                size_t gs = (size_t)wo + (size_t)r2 * STRU + ch * 32 + q * 4;
                uint4 hv = *(const uint4*)(whi + gs);
                uint4 lv = *(const uint4*)(wlo + gs);
                *(uint4*)(smem + WHI_OFF + r2 * TSTR + q * 16) = hv;
                *(uint4*)(smem + WLO_OFF + r2 * TSTR + q * 16) = lv;
            }
            __syncthreads();
            #pragma unroll
            for (int kt = 0; kt < 4; kt++) {
                u32 ko = (u32)(kt * 32);
                u32 ah[4], al[4];
                ldsm4(ah, sbase + AHI_OFF + aoff + ko);
                ldsm4(al, sbase + ALO_OFF + aoff + ko);
                #pragma unroll
                for (int j = 0; j < NT / 2; j++) {
                    u32 bh[4], bl4[4];
                    u32 bo = boff0 + (u32)(j * 16 * TSTR) + ko;
                    ldsm4(bh, sbase + WHI_OFF + bo);
                    ldsm4(bl4, sbase + WLO_OFF + bo);
                    mma16816(acc[2 * j], ah, bh);
                    mma16816(acc[2 * j], ah, bl4);
                    mma16816(acc[2 * j], al, bh);
                    mma16816(acc[2 * j + 1], ah, bh + 2);
                    mma16816(acc[2 * j + 1], ah, bl4 + 2);
                    mma16816(acc[2 * j + 1], al, bh + 2);
                }
            }
        }
    }

    // ---- epilogue ----
    int i0 = row0 + wid * 16 + laneg;
    int i1 = i0 + 8;

    if (MODE == 7) {
        // classifier: relu(acc + b1) then dot with W2 (ex1), bias2 = b2 -> C = logits[N][2]
        float d00 = 0, d10 = 0, d01 = 0, d11 = 0;
        #pragma unroll
        for (int nt = 0; nt < NT; nt++) {
            int c = nt * 8 + kq;
            float w20 = ep.ex1[c], w21 = ep.ex1[c + 1];
            float w30 = ep.ex1[64 + c], w31 = ep.ex1[64 + c + 1];
            float b0 = ep.bias[c], b1v = ep.bias[c + 1];
            float v0 = fmaxf(acc[nt][0] + b0, 0.0f);
            float v1 = fmaxf(acc[nt][1] + b1v, 0.0f);
            d00 += v0 * w20 + v1 * w21;
            d10 += v0 * w30 + v1 * w31;
            v0 = fmaxf(acc[nt][2] + b0, 0.0f);
            v1 = fmaxf(acc[nt][3] + b1v, 0.0f);
            d01 += v0 * w20 + v1 * w21;
            d11 += v0 * w30 + v1 * w31;
        }
        d00 = qsum(d00); d10 = qsum(d10); d01 = qsum(d01); d11 = qsum(d11);
        if ((lane & 3) == 0) {
            float b20 = ep.bias2[0], b21 = ep.bias2[1];
            if (i0 < N) { C[(size_t)i0 * 2] = d00 + b20; C[(size_t)i0 * 2 + 1] = d10 + b21; }
            if (i1 < N) { C[(size_t)i1 * 2] = d01 + b20; C[(size_t)i1 * 2 + 1] = d11 + b21; }
        }
    } else if (MODE == 8) {
        // v = acc + bc + h2 residual; LayerNorm over row; C = h3
        float s0 = 0.0f, s1 = 0.0f;
        #pragma unroll
        for (int nt = 0; nt < NT; nt++) {
            int c = nt * 8 + kq;
            float b0 = ep.bias[c], b1v = ep.bias[c + 1];
            float2 e0 = (i0 < N) ? *(const float2*)&ep.ex1[(size_t)i0 * NOUT + c] : make_float2(0, 0);
            float2 e1 = (i1 < N) ? *(const float2*)&ep.ex1[(size_t)i1 * NOUT + c] : make_float2(0, 0);
            acc[nt][0] += b0 + e0.x;  acc[nt][1] += b1v + e0.y;
            acc[nt][2] += b0 + e1.x;  acc[nt][3] += b1v + e1.y;
            s0 += acc[nt][0] + acc[nt][1];
            s1 += acc[nt][2] + acc[nt][3];
        }
        float mean0 = qsum(s0) * (1.0f / H);
        float mean1 = qsum(s1) * (1.0f / H);
        float vs0 = 0.0f, vs1 = 0.0f;
        #pragma unroll
        for (int nt = 0; nt < NT; nt++) {
            float d;
            d = acc[nt][0] - mean0; vs0 += d * d;
            d = acc[nt][1] - mean0; vs0 += d * d;
            d = acc[nt][2] - mean1; vs1 += d * d;
            d = acc[nt][3] - mean1; vs1 += d * d;
        }
        float inv0 = rsqrtf(qsum(vs0) * (1.0f / H) + 1e-5f);
        float inv1 = rsqrtf(qsum(vs1) * (1.0f / H) + 1e-5f);
        #pragma unroll
        for (int nt = 0; nt < NT; nt++) {
            int c = nt * 8 + kq;
            float gv0 = ep.ex2[c], gv1 = ep.ex2[c + 1];
            float bv0 = ep.ex3[c], bv1 = ep.ex3[c + 1];
            if (i0 < N) {
                float o0 = (acc[nt][0] - mean0) * inv0 * gv0 + bv0;
                float o1 = (acc[nt][1] - mean0) * inv0 * gv1 + bv1;
                *(float2*)&C[(size_t)i0 * NOUT + c] = make_float2(o0, o1);
            }
            if (i1 < N) {
                float o0 = (acc[nt][2] - mean1) * inv1 * gv0 + bv0;
                float o1 = (acc[nt][3] - mean1) * inv1 * gv1 + bv1;
                *(float2*)&C[(size_t)i1 * NOUT + c] = make_float2(o0, o1);
            }
        }
    } else {
        float ntn0 = 0.0f, ntn1 = 0.0f;
        if (MODE == 4) {
            float tmin = __uint_as_float(g_scal[0]);
            float tmax = __uint_as_float(g_scal[1]);
            float inv = 1.0f / (tmax - tmin + 1e-8f);
            bool norm = tmax > tmin;
            if (i0 < N) { float t = ep.nt[i0]; ntn0 = norm ? (t - tmin) * inv : t; }
            if (i1 < N) { float t = ep.nt[i1]; ntn1 = norm ? (t - tmin) * inv : t; }
        }
        #pragma unroll
        for (int nt = 0; nt < NT; nt++) {
            int c = nt * 8 + kq;
            if (i0 < N) epi2<NOUT, MODE>(i0, c, acc[nt][0], acc[nt][1], ep, ntn0, C);
            if (i1 < N) epi2<NOUT, MODE>(i1, c, acc[nt][2], acc[nt][3], ep, ntn1, C);
        }
    }
}

// ---------------- fused GCN gather + path softmax mix + LayerNorm ---------
__global__ void k_gatherp(int N, const float* __restrict__ b_gr, const float* __restrict__ b_gh,
                          const float* __restrict__ lng, const float* __restrict__ lnb) {
    int gw = (blockIdx.x * blockDim.x + threadIdx.x) >> 5;
    int lane = threadIdx.x & 31;
    if (gw >= N) return;
    int i = gw;
    u32 start = g_offs[i];
    u32 cnt = g_degrec[i] + g_deghis[i];
    float4 ar = make_float4(0, 0, 0, 0), ah = make_float4(0, 0, 0, 0);
    for (u32 k = start; k < start + cnt; k++) {
        u32 pk = g_esrc[k];
        float cf = g_ecoef[k];
        int s = (int)(pk >> 1);
        if (pk & 1u) {
            float4 v = *(const float4*)&g_hlrec[(size_t)s * H + lane * 4];
            ar.x += v.x * cf; ar.y += v.y * cf; ar.z += v.z * cf; ar.w += v.w * cf;
        } else {
            float4 v = *(const float4*)&g_hlhis[(size_t)s * H + lane * 4];
            ah.x += v.x * cf; ah.y += v.y * cf; ah.z += v.z * cf; ah.w += v.w * cf;
        }
    }
    float fr = g_disrec[i] * g_disrec[i];
    float fh = g_dishis[i] * g_dishis[i];
    float4 sr = *(const float4*)&g_hlrec[(size_t)i * H + lane * 4];
    float4 sh = *(const float4*)&g_hlhis[(size_t)i * H + lane * 4];
    float4 br = *(const float4*)&b_gr[lane * 4];
    float4 bh = *(const float4*)&b_gh[lane * 4];
    float4 hr, hh;
    hr.x = ar.x + sr.x * fr + br.x; hr.y = ar.y + sr.y * fr + br.y;
    hr.z = ar.z + sr.z * fr + br.z; hr.w = ar.w + sr.w * fr + br.w;
    hh.x = ah.x + sh.x * fh + bh.x; hh.y = ah.y + sh.y * fh + bh.y;
    hh.z = ah.z + sh.z * fh + bh.z; hh.w = ah.w + sh.w * fh + bh.w;
    // path softmax mix + LN (fused)
    float s0 = wsum(hr.x + hr.y + hr.z + hr.w) * (1.0f / H);
    float s1 = wsum(hh.x + hh.y + hh.z + hh.w) * (1.0f / H);
    float m = fmaxf(s0, s1);
    float e0 = expf(s0 - m), e1 = expf(s1 - m);
    float w0 = e0 / (e0 + e1), w1 = e1 / (e0 + e1);
    float4 t;
    t.x = hr.x * w0 + hh.x * w1; t.y = hr.y * w0 + hh.y * w1;
    t.z = hr.z * w0 + hh.z * w1; t.w = hr.w * w0 + hh.w * w1;
    float mean = wsum(t.x + t.y + t.z + t.w) * (1.0f / H);
    float4 d;
    d.x = t.x - mean; d.y = t.y - mean; d.z = t.z - mean; d.w = t.w - mean;
    float var = wsum(d.x * d.x + d.y * d.y + d.z * d.z + d.w * d.w) * (1.0f / H);
    float inv = rsqrtf(var + 1e-5f);
    float4 gv = *(const float4*)&lng[lane * 4];
    float4 bv = *(const float4*)&lnb[lane * 4];
    float4 o;
    o.x = d.x * inv * gv.x + bv.x; o.y = d.y * inv * gv.y + bv.y;
    o.z = d.z * inv * gv.z + bv.z; o.w = d.w * inv * gv.w + bv.w;
    *(float4*)&g_h2[(size_t)i * H + lane * 4] = o;
}

// ---------------- host launcher ----------------
template <int KSRC, int NOUT, int MODE, bool DUAL>
static void tg(const float* A, u32 woff, const float* A2, u32 woff2,
               const u32* whi, const u32* wlo, int N, const Epi& ep, float* C) {
    cudaFuncSetAttribute(k_tgemm<KSRC, NOUT, MODE, DUAL>,
                         cudaFuncAttributeMaxDynamicSharedMemorySize, SMEMSZ);
    k_tgemm<KSRC, NOUT, MODE, DUAL><<<(N + 127) / 128, 256, SMEMSZ>>>(
        A, woff, A2, woff2, whi, wlo, N, ep, C);
}

extern "C" void kernel_launch(void* const* d_in, const int* in_sizes, int n_in,
                              void* d_out, int out_size) {
    const float* x       = (const float*)d_in[0];
    const int*   ei      = (const int*)d_in[1];
    const float* ts      = (const float*)d_in[2];
    const float* mem     = (const float*)d_in[3];
    const float* W_in    = (const float*)d_in[4];
    const float* b_in    = (const float*)d_in[5];
    const float* W_time  = (const float*)d_in[6];
    const float* b_time  = (const float*)d_in[7];
    const float* W_ih    = (const float*)d_in[8];
    const float* W_hh    = (const float*)d_in[9];
    const float* b_ih    = (const float*)d_in[10];
    const float* b_hh    = (const float*)d_in[11];
    const float* W_gr    = (const float*)d_in[12];
    const float* b_gr    = (const float*)d_in[13];
    const float* W_gh    = (const float*)d_in[14];
    const float* b_gh    = (const float*)d_in[15];
    const float* ln_pa_g = (const float*)d_in[16];
    const float* ln_pa_b = (const float*)d_in[17];
    const float* Wv      = (const float*)d_in[18];
    const float* bv      = (const float*)d_in[19];
    const float* Wo      = (const float*)d_in[20];
    const float* bo      = (const float*)d_in[21];
    const float* ln_at_g = (const float*)d_in[22];
    const float* ln_at_b = (const float*)d_in[23];
    const float* W1      = (const float*)d_in[24];
    const float* b1      = (const float*)d_in[25];
    const float* W2p     = (const float*)d_in[26];
    const float* b2      = (const float*)d_in[27];

    const int E = in_sizes[2];
    const int N = in_sizes[0] / F;
    float* out_logits = (float*)d_out;
    float* out_mem = (float*)d_out + (size_t)2 * N;

    float *p_h, *p_r, *p_z, *p_hc, *p_hlrec, *p_hlhis, *p_h2, *p_h3, *p_nt;
    float *p_wc, *p_bc;
    unsigned char* p_upd;
    u32 *p_h1, *p_h2a, *p_h2b, *p_h3a, *p_h3b, *p_whi, *p_wlo;
    cudaGetSymbolAddress((void**)&p_h, g_h);
    cudaGetSymbolAddress((void**)&p_r, g_r);
    cudaGetSymbolAddress((void**)&p_z, g_z);
    cudaGetSymbolAddress((void**)&p_hc, g_hc);
    cudaGetSymbolAddress((void**)&p_hlrec, g_hlrec);
    cudaGetSymbolAddress((void**)&p_hlhis, g_hlhis);
    cudaGetSymbolAddress((void**)&p_h2, g_h2);
    cudaGetSymbolAddress((void**)&p_h3, g_h3);
    cudaGetSymbolAddress((void**)&p_nt, g_nt);
    cudaGetSymbolAddress((void**)&p_upd, g_upd);
    cudaGetSymbolAddress((void**)&p_h1, g_hist1);
    cudaGetSymbolAddress((void**)&p_h2a, g_hist2a);
    cudaGetSymbolAddress((void**)&p_h2b, g_hist2b);
    cudaGetSymbolAddress((void**)&p_h3a, g_hist3a);
    cudaGetSymbolAddress((void**)&p_h3b, g_hist3b);
    cudaGetSymbolAddress((void**)&p_whi, g_whi);
    cudaGetSymbolAddress((void**)&p_wlo, g_wlo);
    cudaGetSymbolAddress((void**)&p_wc, g_wc);
    cudaGetSymbolAddress((void**)&p_bc, g_bc);

    const u32 k0 = (u32)((E - 1) / 2);
    const u32 k1 = (u32)(E / 2);
    const int EB = (E + 255) / 256;
    const int NB1024 = (N + 1023) / 1024;
    const int NWB = (N * 32 + 255) / 256;

    // weight conversion descriptor: 11 real entries (VO uses composed g_wc)
    WC wc;
    const float* wsrcs[11] = {W_in, W_ih, W_ih + H * H, W_ih + 2 * H * H,
                              W_hh, W_hh + H * H, W_hh + 2 * H * H,
                              W_gr, W_gh, p_wc, W1};
    int wK[11]    = {F, H, H, H, H, H, H, H, H, H, H};
    int wrows[11] = {H, H, H, H, H, H, H, H, H, H, 64};
    int run = 0;
    for (int m = 0; m < 11; m++) {
        wc.src[m] = wsrcs[m];
        wc.K[m] = wK[m];
        wc.stride[m] = ((wK[m] + 63) / 64) * 32;
        run += wrows[m] * wc.stride[m];
        wc.end[m] = run;
    }
    wc.src[11] = W1; wc.K[11] = H; wc.stride[11] = 64; wc.end[11] = run;
    wc.total = run;

    // ---- preprocessing ----
    k_init<<<256, 256>>>(N);                                       // 1
    k_compose<<<H, H>>>(Wv, Wo, bv, bo, p_wc, p_bc);               // 2
    k_wconv<<<128, 256>>>(wc, p_whi, p_wlo);                       // 3
    k_edge1<<<1184, 256>>>(ei, ts, E);                             // 4
    k_minmax<<<592, 256>>>(N);                                     // 5
    {
        Epi ep{}; ep.bias = b_hh + 2 * H;                          // 6
        tg<H, H, 1, false>(mem, WOFF_HHC, nullptr, 0, p_whi, p_wlo, N, ep, p_hc);
    }
    k_sel2<<<2, 256>>>(p_h1, p_h1, 16, k0, -1, 2, k1, -1, 4);
    k_hl2<<<888, 256>>>(ts, E);
    k_sel2<<<2, 256>>>(p_h2a, p_h2b, 16, 0, 3, 6, 0, 5, 8);
    k_hl3<<<888, 256>>>(ts, E);
    k_sel2<<<2, 256>>>(p_h3a, p_h3b, 1, 0, 7, 12, 0, 9, 14);
    k_med3<<<1, 1>>>();
    k_deg<<<EB, 256>>>(ei, ts, E);
    k_scan1<<<NB1024, 1024>>>(N);
    k_scan2<<<1, 1>>>(NB1024);
    k_scan3<<<(N + 255) / 256, 256>>>(N);
    k_fill<<<EB, 256>>>(ei, ts, E);

    // ---- h = relu(x@W_in^T + b_in + nt*W_time + b_time) + memory ----
    {
        Epi ep{}; ep.bias = b_in; ep.bias2 = b_time; ep.wtime = W_time; ep.mem = mem; ep.nt = p_nt;
        tg<F, H, 4, false>(x, WOFF_IN, nullptr, 0, p_whi, p_wlo, N, ep, p_h);
    }
    // ---- GRU gates ----
    {
        Epi ep{}; ep.bias = b_ih; ep.bias2 = b_hh;
        tg<H, H, 3, true>(p_h, WOFF_IHR, mem, WOFF_HHR, p_whi, p_wlo, N, ep, p_r);
    }
    {
        Epi ep{}; ep.bias = b_ih + H; ep.bias2 = b_hh + H;
        tg<H, H, 3, true>(p_h, WOFF_IHZ, mem, WOFF_HHZ, p_whi, p_wlo, N, ep, p_z);
    }
    {
        Epi ep{}; ep.bias = b_ih + 2 * H; ep.ex1 = p_hc; ep.ex2 = p_r; ep.ex3 = p_z;
        ep.mem = mem; ep.upd = p_upd;
        tg<H, H, 5, false>(p_h, WOFF_IHC, nullptr, 0, p_whi, p_wlo, N, ep, out_mem);
    }
    // ---- GCN linears + fused gather/pathagg ----
    {
        Epi ep{};
        tg<H, H, 0, false>(p_h, WOFF_GR, nullptr, 0, p_whi, p_wlo, N, ep, p_hlrec);
        tg<H, H, 0, false>(p_h, WOFF_GH, nullptr, 0, p_whi, p_wlo, N, ep, p_hlhis);
    }
    k_gatherp<<<NWB, 256>>>(N, b_gr, b_gh, ln_pa_g, ln_pa_b);
    // ---- attention composed GEMM + residual + LN fused -> h3 ----
    {
        Epi ep{}; ep.bias = p_bc; ep.ex1 = p_h2; ep.ex2 = ln_at_g; ep.ex3 = ln_at_b;
        tg<H, H, 8, false>(p_h2, WOFF_VO, nullptr, 0, p_whi, p_wlo, N, ep, p_h3);
    }
    // ---- classifier + logits fused ----
    {
        Epi ep{}; ep.bias = b1; ep.ex1 = W2p; ep.bias2 = b2;
        tg<H, 64, 7, false>(p_h3, WOFF_W1, nullptr, 0, p_whi, p_wlo, N, ep, out_logits);
    }
}